// round 1
// baseline (speedup 1.0000x reference)
#include <cuda_runtime.h>

#define BB 4
#define CC 512
#define HH 128
#define WW 128
#define NN (HH*WW)      // 16384
#define KCODE 32
#define EPSF 1e-5f

// ---------------- device scratch (no allocations allowed) ----------------
__device__ float g_z[(size_t)BB*CC*NN];        // post conv+bn+relu, [b][c][n]  (134MB)
__device__ float g_assign[(size_t)BB*KCODE*NN];// softmax assignments [b][k][n] (8MB)
__device__ float g_asum[BB*KCODE];             // sum_n assign
__device__ float g_agg[BB*KCODE*CC];           // sum_n assign*z
__device__ float g_feat[BB*CC];
__device__ float g_gamma[BB*CC];

// ---------------- k0: zero the atomically-accumulated buffers ----------------
__global__ void k0_zero() {
    int i = blockIdx.x * blockDim.x + threadIdx.x;
    int total = BB*KCODE*CC;
    for (; i < total; i += gridDim.x * blockDim.x) g_agg[i] = 0.f;
}

// ---------------- k1: conv1x1 GEMM + BN2 + ReLU ----------------
// Z[b][o][n] = relu( bn2( sum_c W[o][c] * X[b][c][n] ) )
// 128x128 block tile, 8x8 thread tile, BK=16.
__global__ __launch_bounds__(256) void k1_conv(
    const float* __restrict__ X, const float* __restrict__ W,
    const float* __restrict__ bg, const float* __restrict__ bb,
    const float* __restrict__ bm, const float* __restrict__ bv)
{
    int b  = blockIdx.z;
    int m0 = blockIdx.y * 128;
    int n0 = blockIdx.x * 128;
    const float* Xb = X + (size_t)b * CC * NN;
    float* Zb = g_z + (size_t)b * CC * NN;

    __shared__ float Ws[16][132];  // [kk][m]
    __shared__ float Xs[16][132];  // [kk][n]

    int tid = threadIdx.x;
    int tx = tid & 15, ty = tid >> 4;

    float acc[8][8] = {};

    int wRow = tid >> 2;           // 0..63
    int wCol = (tid & 3) * 4;      // 0,4,8,12
    int xRow = tid >> 5;           // 0..7
    int xCol = (tid & 31) * 4;

    for (int k0 = 0; k0 < CC; k0 += 16) {
        #pragma unroll
        for (int r = 0; r < 2; r++) {
            int row = wRow + r * 64;
            float4 wv = *reinterpret_cast<const float4*>(&W[(size_t)(m0 + row) * CC + k0 + wCol]);
            Ws[wCol + 0][row] = wv.x;
            Ws[wCol + 1][row] = wv.y;
            Ws[wCol + 2][row] = wv.z;
            Ws[wCol + 3][row] = wv.w;
        }
        #pragma unroll
        for (int r = 0; r < 2; r++) {
            int row = xRow + r * 8;
            float4 xv = *reinterpret_cast<const float4*>(&Xb[(size_t)(k0 + row) * NN + n0 + xCol]);
            *reinterpret_cast<float4*>(&Xs[row][xCol]) = xv;
        }
        __syncthreads();
        #pragma unroll
        for (int kk = 0; kk < 16; kk++) {
            float a[8], c[8];
            #pragma unroll
            for (int i = 0; i < 8; i++) a[i] = Ws[kk][ty * 8 + i];
            #pragma unroll
            for (int j = 0; j < 8; j++) c[j] = Xs[kk][tx * 8 + j];
            #pragma unroll
            for (int i = 0; i < 8; i++)
                #pragma unroll
                for (int j = 0; j < 8; j++)
                    acc[i][j] = fmaf(a[i], c[j], acc[i][j]);
        }
        __syncthreads();
    }

    #pragma unroll
    for (int i = 0; i < 8; i++) {
        int o = m0 + ty * 8 + i;
        float s  = bg[o] * rsqrtf(bv[o] + EPSF);
        float sh = bb[o] - bm[o] * s;
        float4 r0, r1;
        r0.x = fmaxf(fmaf(acc[i][0], s, sh), 0.f);
        r0.y = fmaxf(fmaf(acc[i][1], s, sh), 0.f);
        r0.z = fmaxf(fmaf(acc[i][2], s, sh), 0.f);
        r0.w = fmaxf(fmaf(acc[i][3], s, sh), 0.f);
        r1.x = fmaxf(fmaf(acc[i][4], s, sh), 0.f);
        r1.y = fmaxf(fmaf(acc[i][5], s, sh), 0.f);
        r1.z = fmaxf(fmaf(acc[i][6], s, sh), 0.f);
        r1.w = fmaxf(fmaf(acc[i][7], s, sh), 0.f);
        float* dst = &Zb[(size_t)o * NN + n0 + tx * 8];
        *reinterpret_cast<float4*>(dst)     = r0;
        *reinterpret_cast<float4*>(dst + 4) = r1;
    }
}

// ---------------- k2: xc GEMM + scaled-L2 softmax -> assign ----------------
// One thread handles 2 pixels; codewords staged in 64KB dynamic smem.
__global__ __launch_bounds__(256) void k2_assign(
    const float* __restrict__ cw, const float* __restrict__ scale)
{
    extern __shared__ float sh[];
    float* cw_s = sh;                 // [32][512]
    float* c2_s = sh + KCODE * CC;    // [32]

    int tid = threadIdx.x;
    int b = blockIdx.y;

    const float4* cw4 = reinterpret_cast<const float4*>(cw);
    float4* cws4 = reinterpret_cast<float4*>(cw_s);
    for (int i = tid; i < KCODE * CC / 4; i += 256) cws4[i] = cw4[i];
    __syncthreads();
    if (tid < KCODE) {
        float s = 0.f;
        for (int c = 0; c < CC; c++) { float w = cw_s[tid * CC + c]; s = fmaf(w, w, s); }
        c2_s[tid] = s;
    }
    __syncthreads();

    int n0 = blockIdx.x * 512 + tid;              // second pixel: n0+256
    const float* zb = g_z + (size_t)b * CC * NN;

    float acc0[KCODE], acc1[KCODE];
    #pragma unroll
    for (int k = 0; k < KCODE; k++) { acc0[k] = 0.f; acc1[k] = 0.f; }
    float x20 = 0.f, x21 = 0.f;

    #pragma unroll 4
    for (int c = 0; c < CC; c++) {
        float z0 = zb[(size_t)c * NN + n0];
        float z1 = zb[(size_t)c * NN + n0 + 256];
        x20 = fmaf(z0, z0, x20);
        x21 = fmaf(z1, z1, x21);
        #pragma unroll
        for (int k = 0; k < KCODE; k++) {
            float w = cw_s[k * CC + c];
            acc0[k] = fmaf(w, z0, acc0[k]);
            acc1[k] = fmaf(w, z1, acc1[k]);
        }
    }

    float* ab = g_assign + (size_t)b * KCODE * NN;

    // pixel 0
    {
        float l[KCODE]; float mx = -1e30f;
        #pragma unroll
        for (int k = 0; k < KCODE; k++) {
            float v = __ldg(&scale[k]) * (x20 - 2.f * acc0[k] + c2_s[k]);
            l[k] = v; mx = fmaxf(mx, v);
        }
        float s = 0.f;
        #pragma unroll
        for (int k = 0; k < KCODE; k++) { float e = __expf(l[k] - mx); l[k] = e; s += e; }
        float inv = 1.f / s;
        #pragma unroll
        for (int k = 0; k < KCODE; k++) ab[(size_t)k * NN + n0] = l[k] * inv;
    }
    // pixel 1
    {
        float l[KCODE]; float mx = -1e30f;
        #pragma unroll
        for (int k = 0; k < KCODE; k++) {
            float v = __ldg(&scale[k]) * (x21 - 2.f * acc1[k] + c2_s[k]);
            l[k] = v; mx = fmaxf(mx, v);
        }
        float s = 0.f;
        #pragma unroll
        for (int k = 0; k < KCODE; k++) { float e = __expf(l[k] - mx); l[k] = e; s += e; }
        float inv = 1.f / s;
        #pragma unroll
        for (int k = 0; k < KCODE; k++) ab[(size_t)k * NN + n0 + 256] = l[k] * inv;
    }
}

// ---------------- k2b: asum[b][k] = sum_n assign ----------------
__global__ void k2b_asum() {
    __shared__ float red[256];
    int bk = blockIdx.x;
    const float* a = g_assign + (size_t)bk * NN;
    float s = 0.f;
    for (int n = threadIdx.x; n < NN; n += 256) s += a[n];
    red[threadIdx.x] = s;
    __syncthreads();
    for (int st = 128; st > 0; st >>= 1) {
        if (threadIdx.x < st) red[threadIdx.x] += red[threadIdx.x + st];
        __syncthreads();
    }
    if (threadIdx.x == 0) g_asum[bk] = red[0];
}

// ---------------- k3: agg[b][k][c] = sum_n assign[b][k][n]*z[b][c][n] ----------------
// 32k x 128c tile per block, n split across 16 blocks, fp32 atomic accumulation.
__global__ __launch_bounds__(256) void k3_agg() {
    int b = blockIdx.z;
    int c0 = blockIdx.y * 128;
    int nbase = blockIdx.x * (NN / 16);          // 1024 n per block

    const float* ab = g_assign + (size_t)b * KCODE * NN;
    const float* zb = g_z + (size_t)b * CC * NN;

    __shared__ float As[KCODE][33];
    __shared__ float Zs[128][33];

    int tid = threadIdx.x;
    int lane = tid & 31;
    int wid = tid >> 5;        // 0..7 -> k group

    float acc[4][4] = {};      // [i: k] [j: c], k = wid*4+i, c = c0 + lane + 32*j

    for (int nt = 0; nt < NN / 16; nt += 32) {
        int nidx = nbase + nt + lane;
        #pragma unroll
        for (int p = 0; p < 4; p++) {
            int k = wid + p * 8;
            As[k][lane] = ab[(size_t)k * NN + nidx];
        }
        #pragma unroll
        for (int p = 0; p < 16; p++) {
            int cc = wid + p * 8;
            Zs[cc][lane] = zb[(size_t)(c0 + cc) * NN + nidx];
        }
        __syncthreads();
        #pragma unroll
        for (int q = 0; q < 32; q++) {
            float a[4], zz[4];
            #pragma unroll
            for (int i = 0; i < 4; i++) a[i] = As[wid * 4 + i][q];
            #pragma unroll
            for (int j = 0; j < 4; j++) zz[j] = Zs[lane + 32 * j][q];
            #pragma unroll
            for (int i = 0; i < 4; i++)
                #pragma unroll
                for (int j = 0; j < 4; j++)
                    acc[i][j] = fmaf(a[i], zz[j], acc[i][j]);
        }
        __syncthreads();
    }
    #pragma unroll
    for (int i = 0; i < 4; i++) {
        int k = wid * 4 + i;
        #pragma unroll
        for (int j = 0; j < 4; j++) {
            int c = c0 + lane + 32 * j;
            atomicAdd(&g_agg[((size_t)b * KCODE + k) * CC + c], acc[i][j]);
        }
    }
}

// ---------------- k4a: e = relu(bn1(agg - asum*cw)); feat = mean_k e ----------------
__global__ void k4a_feat(
    const float* __restrict__ cw,
    const float* __restrict__ g1, const float* __restrict__ b1,
    const float* __restrict__ m1, const float* __restrict__ v1,
    float* __restrict__ out_feat)
{
    int b = blockIdx.x;
    int c = threadIdx.x;
    float f = 0.f;
    #pragma unroll
    for (int k = 0; k < KCODE; k++) {
        float a = g_agg[((size_t)b * KCODE + k) * CC + c] - g_asum[b * KCODE + k] * cw[k * CC + c];
        float s = g1[k] * rsqrtf(v1[k] + EPSF);
        float e = fmaxf(fmaf(a - m1[k], s, b1[k]), 0.f);
        f += e;
    }
    f *= (1.f / KCODE);
    g_feat[b * CC + c] = f;
    out_feat[b * CC + c] = f;
}

// ---------------- k4b: gamma = sigmoid(feat @ fc_w^T + fc_b) ----------------
__global__ void k4b_gamma(const float* __restrict__ fw, const float* __restrict__ fb) {
    __shared__ float fs[CC];
    int b = blockIdx.x;
    int o = threadIdx.x;
    fs[o] = g_feat[b * CC + o];
    __syncthreads();
    float acc = fb[o];
    const float* row = fw + (size_t)o * CC;
    #pragma unroll 8
    for (int c = 0; c < CC; c++) acc = fmaf(fs[c], row[c], acc);
    g_gamma[b * CC + o] = 1.f / (1.f + __expf(-acc));
}

// ---------------- k5: out = relu(x * (1 + gamma[b][c])) ----------------
__global__ void k5_gate(const float* __restrict__ x, float* __restrict__ out) {
    int i = blockIdx.x * blockDim.x + threadIdx.x;     // float4 index
    const int total4 = BB * CC * NN / 4;
    if (i >= total4) return;
    int bc = (i * 4) / NN;                              // b*CC + c (NN % 4 == 0)
    float g = 1.f + g_gamma[bc];
    float4 xv = reinterpret_cast<const float4*>(x)[i];
    float4 o;
    o.x = fmaxf(xv.x * g, 0.f);
    o.y = fmaxf(xv.y * g, 0.f);
    o.z = fmaxf(xv.z * g, 0.f);
    o.w = fmaxf(xv.w * g, 0.f);
    reinterpret_cast<float4*>(out)[i] = o;
}

// ---------------- launch ----------------
extern "C" void kernel_launch(void* const* d_in, const int* in_sizes, int n_in,
                              void* d_out, int out_size) {
    const float* x      = (const float*)d_in[0];
    const float* conv_w = (const float*)d_in[1];
    const float* bn2_g  = (const float*)d_in[2];
    const float* bn2_b  = (const float*)d_in[3];
    const float* bn2_m  = (const float*)d_in[4];
    const float* bn2_v  = (const float*)d_in[5];
    const float* cw     = (const float*)d_in[6];
    const float* scale  = (const float*)d_in[7];
    const float* bn1_g  = (const float*)d_in[8];
    const float* bn1_b  = (const float*)d_in[9];
    const float* bn1_m  = (const float*)d_in[10];
    const float* bn1_v  = (const float*)d_in[11];
    const float* fc_w   = (const float*)d_in[12];
    const float* fc_b   = (const float*)d_in[13];
    float* out = (float*)d_out;

    int smem_k2 = (KCODE * CC + KCODE) * (int)sizeof(float);   // ~65.7KB
    cudaFuncSetAttribute(k2_assign, cudaFuncAttributeMaxDynamicSharedMemorySize, smem_k2);

    k0_zero<<<64, 256>>>();
    k1_conv<<<dim3(NN / 128, CC / 128, BB), 256>>>(x, conv_w, bn2_g, bn2_b, bn2_m, bn2_v);
    k2_assign<<<dim3(NN / 512, BB), 256, smem_k2>>>(cw, scale);
    k2b_asum<<<BB * KCODE, 256>>>();
    k3_agg<<<dim3(16, CC / 128, BB), 256>>>();
    k4a_feat<<<BB, CC>>>(cw, bn1_g, bn1_b, bn1_m, bn1_v, out);
    k4b_gamma<<<BB, CC>>>(fc_w, fc_b);
    k5_gate<<<(BB * CC * NN / 4 + 255) / 256, 256>>>(x, out + BB * CC);
}

// round 3
// speedup vs baseline: 1.6100x; 1.6100x over previous
#include <cuda_runtime.h>
#include <cuda_bf16.h>
#include <cstdint>

#define BB 4
#define CC 512
#define HH 128
#define WW 128
#define NN (HH*WW)      // 16384
#define KCODE 32
#define EPSF 1e-5f

// ---------------- device scratch ----------------
__device__ __align__(256) float g_z[(size_t)BB*CC*NN];          // post conv+bn+relu, [b][c][n]
__device__ __align__(256) float g_assign[(size_t)BB*KCODE*NN];  // [b][k][n]
__device__ float g_asum[BB*KCODE];
__device__ float g_agg[BB*KCODE*CC];
__device__ float g_feat[BB*CC];
__device__ float g_gamma[BB*CC];
__device__ __align__(256) __nv_bfloat16 g_whi[CC*CC];           // conv_w split [o][c]
__device__ __align__(256) __nv_bfloat16 g_wlo[CC*CC];
__device__ __align__(256) __nv_bfloat16 g_xthi[(size_t)BB*NN*CC]; // x transposed+split [b][n][c]
__device__ __align__(256) __nv_bfloat16 g_xtlo[(size_t)BB*NN*CC];

// ---------------- helpers ----------------
__device__ __forceinline__ uint32_t smem_u32(const void* p) {
    uint32_t a;
    asm("{ .reg .u64 t; cvta.to.shared.u64 t, %1; cvt.u32.u64 %0, t; }" : "=r"(a) : "l"(p));
    return a;
}
#define SW128(off) ((off) ^ (((off) >> 3) & 0x70))
#define CP16(dst, src) asm volatile("cp.async.cg.shared.global [%0], [%1], 16;" \
    :: "r"(dst), "l"(__cvta_generic_to_global(src)) : "memory")
#define CP_COMMIT() asm volatile("cp.async.commit_group;" ::: "memory")
#define CP_WAIT0()  asm volatile("cp.async.wait_group 0;" ::: "memory")

__device__ __forceinline__ void ldsm4(uint32_t addr, uint32_t* r) {
    asm volatile("ldmatrix.sync.aligned.m8n8.x4.shared.b16 {%0,%1,%2,%3}, [%4];"
        : "=r"(r[0]), "=r"(r[1]), "=r"(r[2]), "=r"(r[3]) : "r"(addr));
}
__device__ __forceinline__ void mma16816(float* c, const uint32_t* a, const uint32_t* b) {
    asm volatile("mma.sync.aligned.m16n8k16.row.col.f32.bf16.bf16.f32 "
        "{%0,%1,%2,%3}, {%4,%5,%6,%7}, {%8,%9}, {%0,%1,%2,%3};"
        : "+f"(c[0]), "+f"(c[1]), "+f"(c[2]), "+f"(c[3])
        : "r"(a[0]), "r"(a[1]), "r"(a[2]), "r"(a[3]), "r"(b[0]), "r"(b[1]));
}

// ---------------- k0: zero agg ----------------
__global__ void k0_zero() {
    int i = blockIdx.x * blockDim.x + threadIdx.x;
    int total = BB*KCODE*CC;
    for (; i < total; i += gridDim.x * blockDim.x) g_agg[i] = 0.f;
}

// ---------------- kc_w: split conv_w into bf16 hi/lo ----------------
__global__ void kc_w(const float* __restrict__ w) {
    int i = blockIdx.x * blockDim.x + threadIdx.x;
    if (i >= CC*CC) return;
    float v = w[i];
    __nv_bfloat16 hi = __float2bfloat16(v);
    __nv_bfloat16 lo = __float2bfloat16(v - __bfloat162float(hi));
    g_whi[i] = hi; g_wlo[i] = lo;
}

// ---------------- kc_x: transpose + split x -> [b][n][c] bf16 hi/lo ----------------
__global__ __launch_bounds__(256) void kc_x(const float* __restrict__ x) {
    __shared__ float tile[64][33];
    int b = blockIdx.z;
    int c0 = blockIdx.y * 64;
    int n0 = blockIdx.x * 32;
    int t = threadIdx.x;
    const float* xb = x + (size_t)b * CC * NN;

    int nn = t & 31, cg = t >> 5;
    #pragma unroll
    for (int i = 0; i < 8; i++) {
        int cc = cg * 8 + i;
        tile[cc][nn] = xb[(size_t)(c0 + cc) * NN + n0 + nn];
    }
    __syncthreads();
    int pc = t & 31, nr = t >> 5;
    #pragma unroll
    for (int i = 0; i < 4; i++) {
        int n = nr + 8 * i;
        float v0 = tile[pc * 2][n], v1 = tile[pc * 2 + 1][n];
        __nv_bfloat16 h0 = __float2bfloat16(v0), h1 = __float2bfloat16(v1);
        __nv_bfloat16 l0 = __float2bfloat16(v0 - __bfloat162float(h0));
        __nv_bfloat16 l1 = __float2bfloat16(v1 - __bfloat162float(h1));
        size_t idx = ((size_t)b * NN + n0 + n) * (CC/2) + (c0/2) + pc;
        reinterpret_cast<__nv_bfloat162*>(g_xthi)[idx] = __nv_bfloat162(h0, h1);
        reinterpret_cast<__nv_bfloat162*>(g_xtlo)[idx] = __nv_bfloat162(l0, l1);
    }
}

// ---------------- k1_mma: bf16-split conv GEMM via mma.sync + BN2 + ReLU ----------------
// Block 128(M=o) x 128(N=n), BK=64, 8 warps in 2(m) x 4(n), warp tile 64x32.
// Smem per stage: A_hi, A_lo, B_hi, B_lo each 128x64 bf16 (16KB, SW128 rows of 128B).
static constexpr int TILE16K = 128 * 128;         // bytes per tile
static constexpr int STAGE = 4 * TILE16K;         // 64KB
static constexpr int SM_K1 = 2 * STAGE;           // 128KB

__global__ __launch_bounds__(256, 1)
void k1_mma(const float* __restrict__ bg, const float* __restrict__ bb_,
            const float* __restrict__ bm, const float* __restrict__ bv)
{
    extern __shared__ char sm[];
    uint32_t sbase = smem_u32(sm);

    int tid = threadIdx.x;
    int lane = tid & 31, wid = tid >> 5;
    int wm = wid & 1, wn = wid >> 1;             // warp tile: rows wm*64, cols wn*32
    int m0 = blockIdx.x * 128;
    int n0 = blockIdx.y * 128;
    int b  = blockIdx.z;

    // per-thread load indices: 1024 16B chunks per tile, 4 per thread per tile
    int lrow[4], lch[4];
    #pragma unroll
    for (int i = 0; i < 4; i++) {
        int q = tid + 256 * i;
        lrow[i] = q >> 3; lch[i] = q & 7;
    }

    auto load_stage = [&](int ch, int st) {
        uint32_t s0 = sbase + st * STAGE;
        #pragma unroll
        for (int i = 0; i < 4; i++) {
            int row = lrow[i], cc = lch[i];
            uint32_t dst = s0 + SW128((uint32_t)(row * 128 + cc * 16));
            size_t aoff = (size_t)(m0 + row) * CC + ch * 64 + cc * 8;
            size_t boff = ((size_t)b * NN + n0 + row) * CC + ch * 64 + cc * 8;
            CP16(dst,               g_whi + aoff);
            CP16(dst + TILE16K,     g_wlo + aoff);
            CP16(dst + 2*TILE16K,   g_xthi + boff);
            CP16(dst + 3*TILE16K,   g_xtlo + boff);
        }
    };

    float acc[4][4][4];
    #pragma unroll
    for (int mi = 0; mi < 4; mi++)
        #pragma unroll
        for (int nj = 0; nj < 4; nj++)
            #pragma unroll
            for (int r = 0; r < 4; r++) acc[mi][nj][r] = 0.f;

    // ldmatrix per-lane row/chunk selectors
    int rowA = lane & 15, chA = lane >> 4;                    // A: 16 rows x 2 k-chunks
    int rowB = ((lane >> 4) << 3) + (lane & 7), chB = (lane >> 3) & 1; // B: 2 n-mats x 2 k-chunks

    load_stage(0, 0);
    CP_COMMIT();

    for (int ch = 0; ch < 8; ch++) {
        CP_WAIT0();
        __syncthreads();
        if (ch < 7) { load_stage(ch + 1, (ch + 1) & 1); CP_COMMIT(); }

        uint32_t s0 = sbase + (ch & 1) * STAGE;
        #pragma unroll
        for (int ks = 0; ks < 4; ks++) {
            uint32_t ahi[4][4], alo[4][4], bhi[2][4], blo[2][4];
            #pragma unroll
            for (int mi = 0; mi < 4; mi++) {
                uint32_t off = SW128((uint32_t)((wm*64 + mi*16 + rowA) * 128 + ks*32 + chA*16));
                ldsm4(s0 + off, ahi[mi]);
                ldsm4(s0 + TILE16K + off, alo[mi]);
            }
            #pragma unroll
            for (int np = 0; np < 2; np++) {
                uint32_t off = SW128((uint32_t)((wn*32 + np*16 + rowB) * 128 + ks*32 + chB*16));
                ldsm4(s0 + 2*TILE16K + off, bhi[np]);
                ldsm4(s0 + 3*TILE16K + off, blo[np]);
            }
            #pragma unroll
            for (int mi = 0; mi < 4; mi++)
                #pragma unroll
                for (int nj = 0; nj < 4; nj++) {
                    const uint32_t* bh = &bhi[nj >> 1][(nj & 1) * 2];
                    const uint32_t* bl = &blo[nj >> 1][(nj & 1) * 2];
                    mma16816(acc[mi][nj], ahi[mi], bh);
                    mma16816(acc[mi][nj], ahi[mi], bl);
                    mma16816(acc[mi][nj], alo[mi], bh);
                }
        }
        __syncthreads();
    }

    // Epilogue: BN2 + ReLU -> g_z[b][o][n]
    float* Zb = g_z + (size_t)b * CC * NN;
    #pragma unroll
    for (int mi = 0; mi < 4; mi++) {
        #pragma unroll
        for (int rr = 0; rr < 2; rr++) {
            int o = m0 + wm*64 + mi*16 + rr*8 + (lane >> 2);
            float sc = bg[o] * rsqrtf(bv[o] + EPSF);
            float sh = bb_[o] - bm[o] * sc;
            float* zr = &Zb[(size_t)o * NN + n0 + wn*32 + (lane & 3) * 2];
            #pragma unroll
            for (int nj = 0; nj < 4; nj++) {
                float2 v;
                v.x = fmaxf(fmaf(acc[mi][nj][rr*2 + 0], sc, sh), 0.f);
                v.y = fmaxf(fmaf(acc[mi][nj][rr*2 + 1], sc, sh), 0.f);
                *reinterpret_cast<float2*>(zr + nj * 8) = v;
            }
        }
    }
}

// ---------------- k2: xc GEMM + scaled-L2 softmax -> assign ----------------
__global__ __launch_bounds__(256) void k2_assign(
    const float* __restrict__ cw, const float* __restrict__ scale)
{
    extern __shared__ float sh[];
    float* cw_s = sh;
    float* c2_s = sh + KCODE * CC;

    int tid = threadIdx.x;
    int b = blockIdx.y;

    const float4* cw4 = reinterpret_cast<const float4*>(cw);
    float4* cws4 = reinterpret_cast<float4*>(cw_s);
    for (int i = tid; i < KCODE * CC / 4; i += 256) cws4[i] = cw4[i];
    __syncthreads();
    if (tid < KCODE) {
        float s = 0.f;
        for (int c = 0; c < CC; c++) { float w = cw_s[tid * CC + c]; s = fmaf(w, w, s); }
        c2_s[tid] = s;
    }
    __syncthreads();

    int n0 = blockIdx.x * 512 + tid;
    const float* zb = g_z + (size_t)b * CC * NN;

    float acc0[KCODE], acc1[KCODE];
    #pragma unroll
    for (int k = 0; k < KCODE; k++) { acc0[k] = 0.f; acc1[k] = 0.f; }
    float x20 = 0.f, x21 = 0.f;

    #pragma unroll 4
    for (int c = 0; c < CC; c++) {
        float z0 = zb[(size_t)c * NN + n0];
        float z1 = zb[(size_t)c * NN + n0 + 256];
        x20 = fmaf(z0, z0, x20);
        x21 = fmaf(z1, z1, x21);
        #pragma unroll
        for (int k = 0; k < KCODE; k++) {
            float w = cw_s[k * CC + c];
            acc0[k] = fmaf(w, z0, acc0[k]);
            acc1[k] = fmaf(w, z1, acc1[k]);
        }
    }

    float* ab = g_assign + (size_t)b * KCODE * NN;
    {
        float l[KCODE]; float mx = -1e30f;
        #pragma unroll
        for (int k = 0; k < KCODE; k++) {
            float v = __ldg(&scale[k]) * (x20 - 2.f * acc0[k] + c2_s[k]);
            l[k] = v; mx = fmaxf(mx, v);
        }
        float s = 0.f;
        #pragma unroll
        for (int k = 0; k < KCODE; k++) { float e = __expf(l[k] - mx); l[k] = e; s += e; }
        float inv = 1.f / s;
        #pragma unroll
        for (int k = 0; k < KCODE; k++) ab[(size_t)k * NN + n0] = l[k] * inv;
    }
    {
        float l[KCODE]; float mx = -1e30f;
        #pragma unroll
        for (int k = 0; k < KCODE; k++) {
            float v = __ldg(&scale[k]) * (x21 - 2.f * acc1[k] + c2_s[k]);
            l[k] = v; mx = fmaxf(mx, v);
        }
        float s = 0.f;
        #pragma unroll
        for (int k = 0; k < KCODE; k++) { float e = __expf(l[k] - mx); l[k] = e; s += e; }
        float inv = 1.f / s;
        #pragma unroll
        for (int k = 0; k < KCODE; k++) ab[(size_t)k * NN + n0 + 256] = l[k] * inv;
    }
}

// ---------------- k2b: asum ----------------
__global__ void k2b_asum() {
    __shared__ float red[256];
    int bk = blockIdx.x;
    const float* a = g_assign + (size_t)bk * NN;
    float s = 0.f;
    for (int n = threadIdx.x; n < NN; n += 256) s += a[n];
    red[threadIdx.x] = s;
    __syncthreads();
    for (int st = 128; st > 0; st >>= 1) {
        if (threadIdx.x < st) red[threadIdx.x] += red[threadIdx.x + st];
        __syncthreads();
    }
    if (threadIdx.x == 0) g_asum[bk] = red[0];
}

// ---------------- k3: agg ----------------
__global__ __launch_bounds__(256) void k3_agg() {
    int b = blockIdx.z;
    int c0 = blockIdx.y * 128;
    int nbase = blockIdx.x * (NN / 16);

    const float* ab = g_assign + (size_t)b * KCODE * NN;
    const float* zb = g_z + (size_t)b * CC * NN;

    __shared__ float As[KCODE][33];
    __shared__ float Zs[128][33];

    int tid = threadIdx.x;
    int lane = tid & 31;
    int wid = tid >> 5;

    float acc[4][4] = {};

    for (int nt = 0; nt < NN / 16; nt += 32) {
        int nidx = nbase + nt + lane;
        #pragma unroll
        for (int p = 0; p < 4; p++) {
            int k = wid + p * 8;
            As[k][lane] = ab[(size_t)k * NN + nidx];
        }
        #pragma unroll
        for (int p = 0; p < 16; p++) {
            int cc = wid + p * 8;
            Zs[cc][lane] = zb[(size_t)(c0 + cc) * NN + nidx];
        }
        __syncthreads();
        #pragma unroll
        for (int q = 0; q < 32; q++) {
            float a[4], zz[4];
            #pragma unroll
            for (int i = 0; i < 4; i++) a[i] = As[wid * 4 + i][q];
            #pragma unroll
            for (int j = 0; j < 4; j++) zz[j] = Zs[lane + 32 * j][q];
            #pragma unroll
            for (int i = 0; i < 4; i++)
                #pragma unroll
                for (int j = 0; j < 4; j++)
                    acc[i][j] = fmaf(a[i], zz[j], acc[i][j]);
        }
        __syncthreads();
    }
    #pragma unroll
    for (int i = 0; i < 4; i++) {
        int k = wid * 4 + i;
        #pragma unroll
        for (int j = 0; j < 4; j++) {
            int c = c0 + lane + 32 * j;
            atomicAdd(&g_agg[((size_t)b * KCODE + k) * CC + c], acc[i][j]);
        }
    }
}

// ---------------- k4a / k4b / k5 ----------------
__global__ void k4a_feat(
    const float* __restrict__ cw,
    const float* __restrict__ g1, const float* __restrict__ b1,
    const float* __restrict__ m1, const float* __restrict__ v1,
    float* __restrict__ out_feat)
{
    int b = blockIdx.x;
    int c = threadIdx.x;
    float f = 0.f;
    #pragma unroll
    for (int k = 0; k < KCODE; k++) {
        float a = g_agg[((size_t)b * KCODE + k) * CC + c] - g_asum[b * KCODE + k] * cw[k * CC + c];
        float s = g1[k] * rsqrtf(v1[k] + EPSF);
        float e = fmaxf(fmaf(a - m1[k], s, b1[k]), 0.f);
        f += e;
    }
    f *= (1.f / KCODE);
    g_feat[b * CC + c] = f;
    out_feat[b * CC + c] = f;
}

__global__ void k4b_gamma(const float* __restrict__ fw, const float* __restrict__ fb) {
    __shared__ float fs[CC];
    int b = blockIdx.x;
    int o = threadIdx.x;
    fs[o] = g_feat[b * CC + o];
    __syncthreads();
    float acc = fb[o];
    const float* row = fw + (size_t)o * CC;
    #pragma unroll 8
    for (int c = 0; c < CC; c++) acc = fmaf(fs[c], row[c], acc);
    g_gamma[b * CC + o] = 1.f / (1.f + __expf(-acc));
}

__global__ void k5_gate(const float* __restrict__ x, float* __restrict__ out) {
    int i = blockIdx.x * blockDim.x + threadIdx.x;
    const int total4 = BB * CC * NN / 4;
    if (i >= total4) return;
    int bc = (i * 4) / NN;
    float g = 1.f + g_gamma[bc];
    float4 xv = reinterpret_cast<const float4*>(x)[i];
    float4 o;
    o.x = fmaxf(xv.x * g, 0.f);
    o.y = fmaxf(xv.y * g, 0.f);
    o.z = fmaxf(xv.z * g, 0.f);
    o.w = fmaxf(xv.w * g, 0.f);
    reinterpret_cast<float4*>(out)[i] = o;
}

// ---------------- launch ----------------
extern "C" void kernel_launch(void* const* d_in, const int* in_sizes, int n_in,
                              void* d_out, int out_size) {
    const float* x      = (const float*)d_in[0];
    const float* conv_w = (const float*)d_in[1];
    const float* bn2_g  = (const float*)d_in[2];
    const float* bn2_b  = (const float*)d_in[3];
    const float* bn2_m  = (const float*)d_in[4];
    const float* bn2_v  = (const float*)d_in[5];
    const float* cw     = (const float*)d_in[6];
    const float* scale  = (const float*)d_in[7];
    const float* bn1_g  = (const float*)d_in[8];
    const float* bn1_b  = (const float*)d_in[9];
    const float* bn1_m  = (const float*)d_in[10];
    const float* bn1_v  = (const float*)d_in[11];
    const float* fc_w   = (const float*)d_in[12];
    const float* fc_b   = (const float*)d_in[13];
    float* out = (float*)d_out;

    int smem_k2 = (KCODE * CC + KCODE) * (int)sizeof(float);
    cudaFuncSetAttribute(k2_assign, cudaFuncAttributeMaxDynamicSharedMemorySize, smem_k2);
    cudaFuncSetAttribute(k1_mma, cudaFuncAttributeMaxDynamicSharedMemorySize, SM_K1);

    k0_zero<<<64, 256>>>();
    kc_w<<<(CC*CC + 255) / 256, 256>>>(conv_w);
    kc_x<<<dim3(NN / 32, CC / 64, BB), 256>>>(x);
    k1_mma<<<dim3(CC / 128, NN / 128, BB), 256, SM_K1>>>(bn2_g, bn2_b, bn2_m, bn2_v);
    k2_assign<<<dim3(NN / 512, BB), 256, smem_k2>>>(cw, scale);
    k2b_asum<<<BB * KCODE, 256>>>();
    k3_agg<<<dim3(16, CC / 128, BB), 256>>>();
    k4a_feat<<<BB, CC>>>(cw, bn1_g, bn1_b, bn1_m, bn1_v, out);
    k4b_gamma<<<BB, CC>>>(fc_w, fc_b);
    k5_gate<<<(BB * CC * NN / 4 + 255) / 256, 256>>>(x, out + BB * CC);
}

// round 4
// speedup vs baseline: 1.8618x; 1.1564x over previous
#include <cuda_runtime.h>
#include <cuda_bf16.h>
#include <cstdint>

#define BB 4
#define CC 512
#define HH 128
#define WW 128
#define NN (HH*WW)      // 16384
#define KCODE 32
#define EPSF 1e-5f

// ---------------- device scratch ----------------
__device__ float g_x2[BB*NN];                               // sum_c z^2 per pixel
__device__ float g_asum[BB*KCODE];
__device__ float g_aggT[BB*CC*KCODE];                       // agg transposed [b][c][k]
__device__ float g_feat[BB*CC];
__device__ float g_gamma[BB*CC];
__device__ float g_c2[KCODE];
__device__ __align__(256) __nv_bfloat16 g_whi[CC*CC];       // conv_w split [o][c]
__device__ __align__(256) __nv_bfloat16 g_wlo[CC*CC];
__device__ __align__(256) __nv_bfloat16 g_cwhi[KCODE*CC];   // codewords split [k][c]
__device__ __align__(256) __nv_bfloat16 g_cwlo[KCODE*CC];
__device__ __align__(256) __nv_bfloat16 g_xthi[(size_t)BB*NN*CC]; // x transposed+split [b][n][c]
__device__ __align__(256) __nv_bfloat16 g_xtlo[(size_t)BB*NN*CC];
__device__ __align__(256) __nv_bfloat16 g_znhi[(size_t)BB*NN*CC]; // z split [b][n][c]
__device__ __align__(256) __nv_bfloat16 g_znlo[(size_t)BB*NN*CC];
__device__ __align__(256) __nv_bfloat16 g_zchi[(size_t)BB*CC*NN]; // z split [b][c][n]
__device__ __align__(256) __nv_bfloat16 g_zclo[(size_t)BB*CC*NN];
__device__ __align__(256) __nv_bfloat16 g_ashi[(size_t)BB*KCODE*NN]; // assign split [b][k][n]
__device__ __align__(256) __nv_bfloat16 g_aslo[(size_t)BB*KCODE*NN];

// ---------------- helpers ----------------
__device__ __forceinline__ uint32_t smem_u32(const void* p) {
    uint32_t a;
    asm("{ .reg .u64 t; cvta.to.shared.u64 t, %1; cvt.u32.u64 %0, t; }" : "=r"(a) : "l"(p));
    return a;
}
#define SW128(off) ((off) ^ (((off) >> 3) & 0x70))
#define CP16(dst, src) asm volatile("cp.async.cg.shared.global [%0], [%1], 16;" \
    :: "r"(dst), "l"(__cvta_generic_to_global(src)) : "memory")
#define CP_COMMIT() asm volatile("cp.async.commit_group;" ::: "memory")
#define CP_WAIT0()  asm volatile("cp.async.wait_group 0;" ::: "memory")

__device__ __forceinline__ void ldsm4(uint32_t addr, uint32_t* r) {
    asm volatile("ldmatrix.sync.aligned.m8n8.x4.shared.b16 {%0,%1,%2,%3}, [%4];"
        : "=r"(r[0]), "=r"(r[1]), "=r"(r[2]), "=r"(r[3]) : "r"(addr));
}
__device__ __forceinline__ void mma16816(float* c, const uint32_t* a, const uint32_t* b) {
    asm volatile("mma.sync.aligned.m16n8k16.row.col.f32.bf16.bf16.f32 "
        "{%0,%1,%2,%3}, {%4,%5,%6,%7}, {%8,%9}, {%0,%1,%2,%3};"
        : "+f"(c[0]), "+f"(c[1]), "+f"(c[2]), "+f"(c[3])
        : "r"(a[0]), "r"(a[1]), "r"(a[2]), "r"(a[3]), "r"(b[0]), "r"(b[1]));
}

// ---------------- k0: zero accumulated buffers ----------------
__global__ void k0_zero() {
    int i = blockIdx.x * blockDim.x + threadIdx.x;
    int stride = gridDim.x * blockDim.x;
    for (int j = i; j < BB*CC*KCODE; j += stride) g_aggT[j] = 0.f;
    for (int j = i; j < BB*NN; j += stride) g_x2[j] = 0.f;
    if (i < BB*KCODE) g_asum[i] = 0.f;
}

// ---------------- kc_w: split conv_w into bf16 hi/lo ----------------
__global__ void kc_w(const float* __restrict__ w) {
    int i = blockIdx.x * blockDim.x + threadIdx.x;
    if (i >= CC*CC) return;
    float v = w[i];
    __nv_bfloat16 hi = __float2bfloat16(v);
    __nv_bfloat16 lo = __float2bfloat16(v - __bfloat162float(hi));
    g_whi[i] = hi; g_wlo[i] = lo;
}

// ---------------- kc_cw: split codewords + c2 ----------------
__global__ void kc_cw(const float* __restrict__ cw) {
    __shared__ float red[128];
    int k = blockIdx.x, t = threadIdx.x;
    float s = 0.f;
    for (int i = t; i < CC; i += 128) {
        float v = cw[k*CC + i];
        __nv_bfloat16 hi = __float2bfloat16(v);
        __nv_bfloat16 lo = __float2bfloat16(v - __bfloat162float(hi));
        g_cwhi[k*CC + i] = hi; g_cwlo[k*CC + i] = lo;
        s = fmaf(v, v, s);
    }
    red[t] = s;
    __syncthreads();
    for (int st = 64; st > 0; st >>= 1) {
        if (t < st) red[t] += red[t + st];
        __syncthreads();
    }
    if (t == 0) g_c2[k] = red[0];
}

// ---------------- kc_x: transpose + split x -> [b][n][c] bf16 hi/lo ----------------
__global__ __launch_bounds__(256) void kc_x(const float* __restrict__ x) {
    __shared__ float tile[64][33];
    int b = blockIdx.z;
    int c0 = blockIdx.y * 64;
    int n0 = blockIdx.x * 32;
    int t = threadIdx.x;
    const float* xb = x + (size_t)b * CC * NN;

    int nn = t & 31, cg = t >> 5;
    #pragma unroll
    for (int i = 0; i < 8; i++) {
        int cc = cg * 8 + i;
        tile[cc][nn] = xb[(size_t)(c0 + cc) * NN + n0 + nn];
    }
    __syncthreads();
    int pc = t & 31, nr = t >> 5;
    #pragma unroll
    for (int i = 0; i < 4; i++) {
        int n = nr + 8 * i;
        float v0 = tile[pc * 2][n], v1 = tile[pc * 2 + 1][n];
        __nv_bfloat16 h0 = __float2bfloat16(v0), h1 = __float2bfloat16(v1);
        __nv_bfloat16 l0 = __float2bfloat16(v0 - __bfloat162float(h0));
        __nv_bfloat16 l1 = __float2bfloat16(v1 - __bfloat162float(h1));
        size_t idx = ((size_t)b * NN + n0 + n) * (CC/2) + (c0/2) + pc;
        reinterpret_cast<__nv_bfloat162*>(g_xthi)[idx] = __nv_bfloat162(h0, h1);
        reinterpret_cast<__nv_bfloat162*>(g_xtlo)[idx] = __nv_bfloat162(l0, l1);
    }
}

// ---------------- k1_mma: conv GEMM (split bf16) + BN2 + ReLU ----------------
// Writes z as split bf16 in [c][n] (direct) and [n][c] (smem transpose) + x2.
static constexpr int TILE16K = 128 * 128;
static constexpr int STAGE = 4 * TILE16K;         // 64KB
static constexpr int SM_K1 = 2 * STAGE;           // 128KB

__global__ __launch_bounds__(256, 1)
void k1_mma(const float* __restrict__ bg, const float* __restrict__ bb_,
            const float* __restrict__ bm, const float* __restrict__ bv)
{
    extern __shared__ char sm[];
    uint32_t sbase = smem_u32(sm);

    int tid = threadIdx.x;
    int lane = tid & 31, wid = tid >> 5;
    int wm = wid & 1, wn = wid >> 1;
    int m0 = blockIdx.x * 128;
    int n0 = blockIdx.y * 128;
    int b  = blockIdx.z;

    int lrow[4], lch[4];
    #pragma unroll
    for (int i = 0; i < 4; i++) {
        int q = tid + 256 * i;
        lrow[i] = q >> 3; lch[i] = q & 7;
    }

    auto load_stage = [&](int ch, int st) {
        uint32_t s0 = sbase + st * STAGE;
        #pragma unroll
        for (int i = 0; i < 4; i++) {
            int row = lrow[i], cc = lch[i];
            uint32_t dst = s0 + SW128((uint32_t)(row * 128 + cc * 16));
            size_t aoff = (size_t)(m0 + row) * CC + ch * 64 + cc * 8;
            size_t boff = ((size_t)b * NN + n0 + row) * CC + ch * 64 + cc * 8;
            CP16(dst,               g_whi + aoff);
            CP16(dst + TILE16K,     g_wlo + aoff);
            CP16(dst + 2*TILE16K,   g_xthi + boff);
            CP16(dst + 3*TILE16K,   g_xtlo + boff);
        }
    };

    float acc[4][4][4];
    #pragma unroll
    for (int mi = 0; mi < 4; mi++)
        #pragma unroll
        for (int nj = 0; nj < 4; nj++)
            #pragma unroll
            for (int r = 0; r < 4; r++) acc[mi][nj][r] = 0.f;

    int rowA = lane & 15, chA = lane >> 4;
    int rowB = ((lane >> 4) << 3) + (lane & 7), chB = (lane >> 3) & 1;

    load_stage(0, 0);
    CP_COMMIT();

    for (int ch = 0; ch < 8; ch++) {
        CP_WAIT0();
        __syncthreads();
        if (ch < 7) { load_stage(ch + 1, (ch + 1) & 1); CP_COMMIT(); }

        uint32_t s0 = sbase + (ch & 1) * STAGE;
        #pragma unroll
        for (int ks = 0; ks < 4; ks++) {
            uint32_t ahi[4][4], alo[4][4], bhi[2][4], blo[2][4];
            #pragma unroll
            for (int mi = 0; mi < 4; mi++) {
                uint32_t off = SW128((uint32_t)((wm*64 + mi*16 + rowA) * 128 + ks*32 + chA*16));
                ldsm4(s0 + off, ahi[mi]);
                ldsm4(s0 + TILE16K + off, alo[mi]);
            }
            #pragma unroll
            for (int np = 0; np < 2; np++) {
                uint32_t off = SW128((uint32_t)((wn*32 + np*16 + rowB) * 128 + ks*32 + chB*16));
                ldsm4(s0 + 2*TILE16K + off, bhi[np]);
                ldsm4(s0 + 3*TILE16K + off, blo[np]);
            }
            #pragma unroll
            for (int mi = 0; mi < 4; mi++)
                #pragma unroll
                for (int nj = 0; nj < 4; nj++) {
                    const uint32_t* bh = &bhi[nj >> 1][(nj & 1) * 2];
                    const uint32_t* bl = &blo[nj >> 1][(nj & 1) * 2];
                    mma16816(acc[mi][nj], ahi[mi], bh);
                    mma16816(acc[mi][nj], ahi[mi], bl);
                    mma16816(acc[mi][nj], alo[mi], bh);
                }
        }
        __syncthreads();
    }

    // ---- Epilogue: BN2+ReLU; write z split bf16 [c][n] + stage [n][o]; x2 ----
    __nv_bfloat16* sh_hi = reinterpret_cast<__nv_bfloat16*>(sm);
    __nv_bfloat16* sh_lo = sh_hi + 128 * 136;

    float v2acc[8];
    #pragma unroll
    for (int j = 0; j < 8; j++) v2acc[j] = 0.f;

    #pragma unroll
    for (int mi = 0; mi < 4; mi++) {
        #pragma unroll
        for (int rr = 0; rr < 2; rr++) {
            int o_loc = wm*64 + mi*16 + rr*8 + (lane >> 2);
            int o = m0 + o_loc;
            float sc = bg[o] * rsqrtf(bv[o] + EPSF);
            float sh2 = bb_[o] - bm[o] * sc;
            #pragma unroll
            for (int nj = 0; nj < 4; nj++) {
                float z0 = fmaxf(fmaf(acc[mi][nj][rr*2 + 0], sc, sh2), 0.f);
                float z1 = fmaxf(fmaf(acc[mi][nj][rr*2 + 1], sc, sh2), 0.f);
                v2acc[nj*2 + 0] += z0 * z0;
                v2acc[nj*2 + 1] += z1 * z1;
                __nv_bfloat16 h0 = __float2bfloat16(z0), h1 = __float2bfloat16(z1);
                __nv_bfloat16 l0 = __float2bfloat16(z0 - __bfloat162float(h0));
                __nv_bfloat16 l1 = __float2bfloat16(z1 - __bfloat162float(h1));
                int n_loc = wn*32 + nj*8 + (lane & 3) * 2;
                size_t zi = ((size_t)(b*CC + o)) * NN + n0 + n_loc;
                *reinterpret_cast<__nv_bfloat162*>(&g_zchi[zi]) = __nv_bfloat162(h0, h1);
                *reinterpret_cast<__nv_bfloat162*>(&g_zclo[zi]) = __nv_bfloat162(l0, l1);
                sh_hi[(n_loc + 0) * 136 + o_loc] = h0;
                sh_hi[(n_loc + 1) * 136 + o_loc] = h1;
                sh_lo[(n_loc + 0) * 136 + o_loc] = l0;
                sh_lo[(n_loc + 1) * 136 + o_loc] = l1;
            }
        }
    }
    // x2: reduce over the 8 o-groups (lane>>2) then atomicAdd per n
    #pragma unroll
    for (int j = 0; j < 8; j++) {
        v2acc[j] += __shfl_xor_sync(0xffffffffu, v2acc[j], 4);
        v2acc[j] += __shfl_xor_sync(0xffffffffu, v2acc[j], 8);
        v2acc[j] += __shfl_xor_sync(0xffffffffu, v2acc[j], 16);
    }
    if ((lane >> 2) == 0) {
        #pragma unroll
        for (int j = 0; j < 8; j++) {
            int n_loc = wn*32 + (j >> 1) * 8 + (lane & 3) * 2 + (j & 1);
            atomicAdd(&g_x2[b*NN + n0 + n_loc], v2acc[j]);
        }
    }
    __syncthreads();
    // [n][c] stores from staging
    #pragma unroll
    for (int i = 0; i < 8; i++) {
        int idx = tid + 256 * i;
        int row = idx >> 4, c16 = idx & 15;
        uint4 vh = *reinterpret_cast<const uint4*>(sh_hi + row * 136 + c16 * 8);
        uint4 vl = *reinterpret_cast<const uint4*>(sh_lo + row * 136 + c16 * 8);
        size_t di = ((size_t)b*NN + n0 + row) * CC + m0 + c16 * 8;
        *reinterpret_cast<uint4*>(&g_znhi[di]) = vh;
        *reinterpret_cast<uint4*>(&g_znlo[di]) = vl;
    }
}

// ---------------- k2_mma: assignment via tensor cores + fused softmax ----------------
// C[codes 32][pixels 256], A = codewords (smem resident), B = z[n][c] chunks.
static constexpr int K2_CW_HI = 0;
static constexpr int K2_CW_LO = 32768;
static constexpr int K2_ZST   = 65536;          // 2 stages x 64KB
static constexpr int K2_X2S   = 196608;
static constexpr int K2_ASUM  = 197632;
static constexpr int SM_K2    = 197760;

__global__ __launch_bounds__(256, 1)
void k2_mma(const float* __restrict__ scale)
{
    extern __shared__ char sm[];
    uint32_t sbase = smem_u32(sm);
    int tid = threadIdx.x, lane = tid & 31, w = tid >> 5;
    int b = blockIdx.y;
    int n0 = blockIdx.x * 256;
    int q = lane >> 2;

    if (tid < 32) *reinterpret_cast<float*>(sm + K2_ASUM + tid*4) = 0.f;
    // cw -> smem with 1024B-row swizzle
    const uint4* cwh4 = reinterpret_cast<const uint4*>(g_cwhi);
    const uint4* cwl4 = reinterpret_cast<const uint4*>(g_cwlo);
    #pragma unroll
    for (int i = 0; i < 8; i++) {
        int idx = tid + 256 * i;
        int row = idx >> 6, cb = idx & 63;
        uint32_t off = (uint32_t)(row * 1024 + ((cb * 16) ^ ((row & 7) << 4)));
        *reinterpret_cast<uint4*>(sm + K2_CW_HI + off) = cwh4[row * 64 + cb];
        *reinterpret_cast<uint4*>(sm + K2_CW_LO + off) = cwl4[row * 64 + cb];
    }
    *reinterpret_cast<float*>(sm + K2_X2S + tid*4) = g_x2[b*NN + n0 + tid];

    auto load_z = [&](int ch, int st) {
        uint32_t s0 = sbase + K2_ZST + st * 65536;
        #pragma unroll
        for (int i = 0; i < 8; i++) {
            int idx = tid + 256 * i;
            int row = idx >> 3, col = idx & 7;
            uint32_t dst = s0 + SW128((uint32_t)(row * 128 + col * 16));
            size_t src = ((size_t)b*NN + n0 + row) * CC + ch * 64 + col * 8;
            CP16(dst,         g_znhi + src);
            CP16(dst + 32768, g_znlo + src);
        }
    };

    float acc[2][4][4];
    #pragma unroll
    for (int mf = 0; mf < 2; mf++)
        #pragma unroll
        for (int nj = 0; nj < 4; nj++)
            #pragma unroll
            for (int r = 0; r < 4; r++) acc[mf][nj][r] = 0.f;

    load_z(0, 0);
    CP_COMMIT();

    for (int ch = 0; ch < 8; ch++) {
        CP_WAIT0();
        __syncthreads();
        if (ch < 7) { load_z(ch + 1, (ch + 1) & 1); CP_COMMIT(); }
        uint32_t zs = sbase + K2_ZST + (ch & 1) * 65536;
        #pragma unroll
        for (int ks = 0; ks < 4; ks++) {
            uint32_t ah[2][4], al[2][4], bh[2][4], bl[2][4];
            #pragma unroll
            for (int mf = 0; mf < 2; mf++) {
                int code = mf * 16 + (lane & 15);
                uint32_t off = (uint32_t)(code * 1024 +
                    ((ch*128 + ks*32 + (lane >> 4) * 16) ^ ((code & 7) << 4)));
                ldsm4(sbase + K2_CW_HI + off, ah[mf]);
                ldsm4(sbase + K2_CW_LO + off, al[mf]);
            }
            #pragma unroll
            for (int p = 0; p < 2; p++) {
                int row = w*32 + p*16 + ((lane >> 4) << 3) + (lane & 7);
                uint32_t off = SW128((uint32_t)(row * 128 + ks*32 + ((lane >> 3) & 1) * 16));
                ldsm4(zs + off, bh[p]);
                ldsm4(zs + off + 32768, bl[p]);
            }
            #pragma unroll
            for (int mf = 0; mf < 2; mf++)
                #pragma unroll
                for (int nj = 0; nj < 4; nj++) {
                    const uint32_t* Bh = &bh[nj >> 1][(nj & 1) * 2];
                    const uint32_t* Bl = &bl[nj >> 1][(nj & 1) * 2];
                    mma16816(acc[mf][nj], ah[mf], Bh);
                    mma16816(acc[mf][nj], ah[mf], Bl);
                    mma16816(acc[mf][nj], al[mf], Bh);
                }
        }
        __syncthreads();
    }

    // ---- softmax over codes (m axis) ----
    float s4[4], c24[4];
    #pragma unroll
    for (int ci = 0; ci < 4; ci++) {
        s4[ci] = __ldg(&scale[q + 8*ci]);
        c24[ci] = g_c2[q + 8*ci];
    }
    float l[4][8];
    #pragma unroll
    for (int mf = 0; mf < 2; mf++)
        #pragma unroll
        for (int nj = 0; nj < 4; nj++)
            #pragma unroll
            for (int r = 0; r < 4; r++) {
                int ci = mf*2 + (r >> 1);
                int j  = nj*2 + (r & 1);
                int col = nj*8 + (lane & 3)*2 + (r & 1);
                float x2v = *reinterpret_cast<const float*>(sm + K2_X2S + (w*32 + col)*4);
                l[ci][j] = s4[ci] * (x2v - 2.f * acc[mf][nj][r] + c24[ci]);
            }
    float mx[8], sme[8], inv[8];
    #pragma unroll
    for (int j = 0; j < 8; j++) {
        mx[j] = fmaxf(fmaxf(l[0][j], l[1][j]), fmaxf(l[2][j], l[3][j]));
        mx[j] = fmaxf(mx[j], __shfl_xor_sync(0xffffffffu, mx[j], 4));
        mx[j] = fmaxf(mx[j], __shfl_xor_sync(0xffffffffu, mx[j], 8));
        mx[j] = fmaxf(mx[j], __shfl_xor_sync(0xffffffffu, mx[j], 16));
    }
    #pragma unroll
    for (int j = 0; j < 8; j++) {
        sme[j] = 0.f;
        #pragma unroll
        for (int ci = 0; ci < 4; ci++) {
            float e = __expf(l[ci][j] - mx[j]);
            l[ci][j] = e; sme[j] += e;
        }
        sme[j] += __shfl_xor_sync(0xffffffffu, sme[j], 4);
        sme[j] += __shfl_xor_sync(0xffffffffu, sme[j], 8);
        sme[j] += __shfl_xor_sync(0xffffffffu, sme[j], 16);
        inv[j] = 1.f / sme[j];
    }
    // stage assign bf16 hi/lo [32][256] (reuse z-stage smem) + asum
    __nv_bfloat16* as_hi = reinterpret_cast<__nv_bfloat16*>(sm + K2_ZST);
    __nv_bfloat16* as_lo = as_hi + 32 * 256;
    float apart[4];
    #pragma unroll
    for (int ci = 0; ci < 4; ci++) apart[ci] = 0.f;
    #pragma unroll
    for (int ci = 0; ci < 4; ci++)
        #pragma unroll
        for (int j = 0; j < 8; j++) {
            float av = l[ci][j] * inv[j];
            apart[ci] += av;
            int code = q + 8*ci;
            int pix = w*32 + (j >> 1)*8 + (lane & 3)*2 + (j & 1);
            __nv_bfloat16 hv = __float2bfloat16(av);
            __nv_bfloat16 lv = __float2bfloat16(av - __bfloat162float(hv));
            as_hi[code*256 + pix] = hv;
            as_lo[code*256 + pix] = lv;
        }
    #pragma unroll
    for (int ci = 0; ci < 4; ci++) {
        apart[ci] += __shfl_xor_sync(0xffffffffu, apart[ci], 1);
        apart[ci] += __shfl_xor_sync(0xffffffffu, apart[ci], 2);
    }
    if ((lane & 3) == 0) {
        #pragma unroll
        for (int ci = 0; ci < 4; ci++)
            atomicAdd(reinterpret_cast<float*>(sm + K2_ASUM + (q + 8*ci)*4), apart[ci]);
    }
    __syncthreads();
    #pragma unroll
    for (int i = 0; i < 4; i++) {
        int idx = tid + 256 * i;
        int row = idx >> 5, c16 = idx & 31;
        size_t di = ((size_t)(b*KCODE + row)) * NN + n0 + c16 * 8;
        *reinterpret_cast<uint4*>(&g_ashi[di]) = *reinterpret_cast<const uint4*>(as_hi + idx*8);
        *reinterpret_cast<uint4*>(&g_aslo[di]) = *reinterpret_cast<const uint4*>(as_lo + idx*8);
    }
    if (tid < 32)
        atomicAdd(&g_asum[b*KCODE + tid], *reinterpret_cast<float*>(sm + K2_ASUM + tid*4));
}

// ---------------- k3_mma: agg via tensor cores ----------------
// C[c][codes], A = z[c][n], B = assign[k][n]. atomicAdd into aggT[b][c][k].
static constexpr int K3_STG = 73728;   // z_hi 32K | z_lo 32K | a_hi 4K | a_lo 4K
static constexpr int SM_K3 = 2 * K3_STG;

__global__ __launch_bounds__(256, 1)
void k3_mma()
{
    extern __shared__ char sm[];
    uint32_t sbase = smem_u32(sm);
    int tid = threadIdx.x, lane = tid & 31, w = tid >> 5;
    int c0 = blockIdx.x * 256;
    int pbase = blockIdx.y * 1024;
    int b = blockIdx.z;

    auto load = [&](int chunk, int st) {
        uint32_t s0 = sbase + st * K3_STG;
        int pix = pbase + chunk * 64;
        #pragma unroll
        for (int i = 0; i < 8; i++) {
            int idx = tid + 256 * i;
            int row = idx >> 3, col = idx & 7;
            uint32_t dst = s0 + SW128((uint32_t)(row * 128 + col * 16));
            size_t src = ((size_t)(b*CC + c0 + row)) * NN + pix + col * 8;
            CP16(dst,         g_zchi + src);
            CP16(dst + 32768, g_zclo + src);
        }
        {
            int row = tid >> 3, col = tid & 7;
            uint32_t dst = s0 + 65536 + SW128((uint32_t)(row * 128 + col * 16));
            size_t src = ((size_t)(b*KCODE + row)) * NN + pix + col * 8;
            CP16(dst,        g_ashi + src);
            CP16(dst + 4096, g_aslo + src);
        }
    };

    float acc[2][4][4];
    #pragma unroll
    for (int mf = 0; mf < 2; mf++)
        #pragma unroll
        for (int nj = 0; nj < 4; nj++)
            #pragma unroll
            for (int r = 0; r < 4; r++) acc[mf][nj][r] = 0.f;

    load(0, 0);
    CP_COMMIT();

    for (int chunk = 0; chunk < 16; chunk++) {
        CP_WAIT0();
        __syncthreads();
        if (chunk < 15) { load(chunk + 1, (chunk + 1) & 1); CP_COMMIT(); }
        uint32_t s0 = sbase + (chunk & 1) * K3_STG;
        #pragma unroll
        for (int ks = 0; ks < 4; ks++) {
            uint32_t zh[2][4], zl[2][4], ah[2][4], al[2][4];
            #pragma unroll
            for (int mf = 0; mf < 2; mf++) {
                int row = w*32 + mf*16 + (lane & 15);
                uint32_t off = SW128((uint32_t)(row * 128 + ks*32 + (lane >> 4) * 16));
                ldsm4(s0 + off, zh[mf]);
                ldsm4(s0 + 32768 + off, zl[mf]);
            }
            #pragma unroll
            for (int p = 0; p < 2; p++) {
                int row = p*16 + ((lane >> 4) << 3) + (lane & 7);
                uint32_t off = SW128((uint32_t)(row * 128 + ks*32 + ((lane >> 3) & 1) * 16));
                ldsm4(s0 + 65536 + off, ah[p]);
                ldsm4(s0 + 69632 + off, al[p]);
            }
            #pragma unroll
            for (int mf = 0; mf < 2; mf++)
                #pragma unroll
                for (int nj = 0; nj < 4; nj++) {
                    const uint32_t* Bh = &ah[nj >> 1][(nj & 1) * 2];
                    const uint32_t* Bl = &al[nj >> 1][(nj & 1) * 2];
                    mma16816(acc[mf][nj], zh[mf], Bh);
                    mma16816(acc[mf][nj], zh[mf], Bl);
                    mma16816(acc[mf][nj], zl[mf], Bh);
                }
        }
        __syncthreads();
    }

    #pragma unroll
    for (int mf = 0; mf < 2; mf++)
        #pragma unroll
        for (int nj = 0; nj < 4; nj++)
            #pragma unroll
            for (int r = 0; r < 4; r++) {
                int c = c0 + w*32 + mf*16 + (lane >> 2) + (r >> 1) * 8;
                int k = nj*8 + (lane & 3)*2 + (r & 1);
                atomicAdd(&g_aggT[((size_t)b*CC + c)*KCODE + k], acc[mf][nj][r]);
            }
}

// ---------------- k4a / k4b / k5 ----------------
__global__ void k4a_feat(
    const float* __restrict__ cw,
    const float* __restrict__ g1, const float* __restrict__ b1,
    const float* __restrict__ m1, const float* __restrict__ v1,
    float* __restrict__ out_feat)
{
    int b = blockIdx.x;
    int c = threadIdx.x;
    float f = 0.f;
    #pragma unroll
    for (int k = 0; k < KCODE; k++) {
        float a = g_aggT[((size_t)b*CC + c)*KCODE + k] - g_asum[b*KCODE + k] * cw[k*CC + c];
        float s = g1[k] * rsqrtf(v1[k] + EPSF);
        float e = fmaxf(fmaf(a - m1[k], s, b1[k]), 0.f);
        f += e;
    }
    f *= (1.f / KCODE);
    g_feat[b*CC + c] = f;
    out_feat[b*CC + c] = f;
}

__global__ void k4b_gamma(const float* __restrict__ fw, const float* __restrict__ fb) {
    __shared__ float fs[CC];
    int b = blockIdx.x;
    int o = threadIdx.x;
    fs[o] = g_feat[b*CC + o];
    __syncthreads();
    float acc = fb[o];
    const float* row = fw + (size_t)o * CC;
    #pragma unroll 8
    for (int c = 0; c < CC; c++) acc = fmaf(fs[c], row[c], acc);
    g_gamma[b*CC + o] = 1.f / (1.f + __expf(-acc));
}

__global__ void k5_gate(const float* __restrict__ x, float* __restrict__ out) {
    int i = blockIdx.x * blockDim.x + threadIdx.x;
    const int total4 = BB * CC * NN / 4;
    if (i >= total4) return;
    int bc = (i * 4) / NN;
    float g = 1.f + g_gamma[bc];
    float4 xv = reinterpret_cast<const float4*>(x)[i];
    float4 o;
    o.x = fmaxf(xv.x * g, 0.f);
    o.y = fmaxf(xv.y * g, 0.f);
    o.z = fmaxf(xv.z * g, 0.f);
    o.w = fmaxf(xv.w * g, 0.f);
    reinterpret_cast<float4*>(out)[i] = o;
}

// ---------------- launch ----------------
extern "C" void kernel_launch(void* const* d_in, const int* in_sizes, int n_in,
                              void* d_out, int out_size) {
    const float* x      = (const float*)d_in[0];
    const float* conv_w = (const float*)d_in[1];
    const float* bn2_g  = (const float*)d_in[2];
    const float* bn2_b  = (const float*)d_in[3];
    const float* bn2_m  = (const float*)d_in[4];
    const float* bn2_v  = (const float*)d_in[5];
    const float* cw     = (const float*)d_in[6];
    const float* scale  = (const float*)d_in[7];
    const float* bn1_g  = (const float*)d_in[8];
    const float* bn1_b  = (const float*)d_in[9];
    const float* bn1_m  = (const float*)d_in[10];
    const float* bn1_v  = (const float*)d_in[11];
    const float* fc_w   = (const float*)d_in[12];
    const float* fc_b   = (const float*)d_in[13];
    float* out = (float*)d_out;

    cudaFuncSetAttribute(k1_mma, cudaFuncAttributeMaxDynamicSharedMemorySize, SM_K1);
    cudaFuncSetAttribute(k2_mma, cudaFuncAttributeMaxDynamicSharedMemorySize, SM_K2);
    cudaFuncSetAttribute(k3_mma, cudaFuncAttributeMaxDynamicSharedMemorySize, SM_K3);

    k0_zero<<<128, 256>>>();
    kc_w<<<(CC*CC + 255) / 256, 256>>>(conv_w);
    kc_cw<<<KCODE, 128>>>(cw);
    kc_x<<<dim3(NN / 32, CC / 64, BB), 256>>>(x);
    k1_mma<<<dim3(CC / 128, NN / 128, BB), 256, SM_K1>>>(bn2_g, bn2_b, bn2_m, bn2_v);
    k2_mma<<<dim3(NN / 256, BB), 256, SM_K2>>>(scale);
    k3_mma<<<dim3(CC / 256, NN / 1024, BB), 256, SM_K3>>>();
    k4a_feat<<<BB, CC>>>(cw, bn1_g, bn1_b, bn1_m, bn1_v, out);
    k4b_gamma<<<BB, CC>>>(fc_w, fc_b);
    k5_gate<<<(BB * CC * NN / 4 + 255) / 256, 256>>>(x, out + BB * CC);
}

// round 5
// speedup vs baseline: 1.9761x; 1.0614x over previous
#include <cuda_runtime.h>
#include <cuda_bf16.h>
#include <cstdint>

#define BB 4
#define CC 512
#define HH 128
#define WW 128
#define NN (HH*WW)      // 16384
#define KCODE 32
#define EPSF 1e-5f

// ---------------- device scratch ----------------
__device__ float g_x2[BB*NN];                               // sum_c z^2 per pixel
__device__ float g_asum[BB*KCODE];
__device__ float g_aggT[BB*CC*KCODE];                       // agg transposed [b][c][k]
__device__ float g_feat[BB*CC];
__device__ float g_gamma[BB*CC];
__device__ float g_c2[KCODE];
__device__ __align__(256) __nv_bfloat16 g_whi[CC*CC];       // conv_w split [o][c]
__device__ __align__(256) __nv_bfloat16 g_wlo[CC*CC];
__device__ __align__(256) __nv_bfloat16 g_cwhi[KCODE*CC];   // codewords split [k][c]
__device__ __align__(256) __nv_bfloat16 g_cwlo[KCODE*CC];
__device__ __align__(256) __nv_bfloat16 g_xthi[(size_t)BB*NN*CC]; // x transposed+split [b][n][c]
__device__ __align__(256) __nv_bfloat16 g_xtlo[(size_t)BB*NN*CC];
__device__ __align__(256) __nv_bfloat16 g_znhi[(size_t)BB*NN*CC]; // z split [b][n][c]
__device__ __align__(256) __nv_bfloat16 g_znlo[(size_t)BB*NN*CC];
__device__ __align__(256) __nv_bfloat16 g_ashi[(size_t)BB*KCODE*NN]; // assign split [b][k][n]
__device__ __align__(256) __nv_bfloat16 g_aslo[(size_t)BB*KCODE*NN];

// ---------------- helpers ----------------
__device__ __forceinline__ uint32_t smem_u32(const void* p) {
    uint32_t a;
    asm("{ .reg .u64 t; cvta.to.shared.u64 t, %1; cvt.u32.u64 %0, t; }" : "=r"(a) : "l"(p));
    return a;
}
#define SW128(off) ((off) ^ (((off) >> 3) & 0x70))
#define CP16(dst, src) asm volatile("cp.async.cg.shared.global [%0], [%1], 16;" \
    :: "r"(dst), "l"(__cvta_generic_to_global(src)) : "memory")
#define CP_COMMIT() asm volatile("cp.async.commit_group;" ::: "memory")
#define CP_WAIT0()  asm volatile("cp.async.wait_group 0;" ::: "memory")
#define CP_WAIT1()  asm volatile("cp.async.wait_group 1;" ::: "memory")

__device__ __forceinline__ void ldsm4(uint32_t addr, uint32_t* r) {
    asm volatile("ldmatrix.sync.aligned.m8n8.x4.shared.b16 {%0,%1,%2,%3}, [%4];"
        : "=r"(r[0]), "=r"(r[1]), "=r"(r[2]), "=r"(r[3]) : "r"(addr));
}
__device__ __forceinline__ void ldsm4t(uint32_t addr, uint32_t* r) {
    asm volatile("ldmatrix.sync.aligned.m8n8.x4.trans.shared.b16 {%0,%1,%2,%3}, [%4];"
        : "=r"(r[0]), "=r"(r[1]), "=r"(r[2]), "=r"(r[3]) : "r"(addr));
}
__device__ __forceinline__ void mma16816(float* c, const uint32_t* a, const uint32_t* b) {
    asm volatile("mma.sync.aligned.m16n8k16.row.col.f32.bf16.bf16.f32 "
        "{%0,%1,%2,%3}, {%4,%5,%6,%7}, {%8,%9}, {%0,%1,%2,%3};"
        : "+f"(c[0]), "+f"(c[1]), "+f"(c[2]), "+f"(c[3])
        : "r"(a[0]), "r"(a[1]), "r"(a[2]), "r"(a[3]), "r"(b[0]), "r"(b[1]));
}

// ---------------- k0: zero accumulated buffers ----------------
__global__ void k0_zero() {
    int i = blockIdx.x * blockDim.x + threadIdx.x;
    int stride = gridDim.x * blockDim.x;
    for (int j = i; j < BB*CC*KCODE; j += stride) g_aggT[j] = 0.f;
    for (int j = i; j < BB*NN; j += stride) g_x2[j] = 0.f;
    if (i < BB*KCODE) g_asum[i] = 0.f;
}

// ---------------- kc_w: split conv_w into bf16 hi/lo ----------------
__global__ void kc_w(const float* __restrict__ w) {
    int i = blockIdx.x * blockDim.x + threadIdx.x;
    if (i >= CC*CC) return;
    float v = w[i];
    __nv_bfloat16 hi = __float2bfloat16(v);
    __nv_bfloat16 lo = __float2bfloat16(v - __bfloat162float(hi));
    g_whi[i] = hi; g_wlo[i] = lo;
}

// ---------------- kc_cw: split codewords + c2 ----------------
__global__ void kc_cw(const float* __restrict__ cw) {
    __shared__ float red[128];
    int k = blockIdx.x, t = threadIdx.x;
    float s = 0.f;
    for (int i = t; i < CC; i += 128) {
        float v = cw[k*CC + i];
        __nv_bfloat16 hi = __float2bfloat16(v);
        __nv_bfloat16 lo = __float2bfloat16(v - __bfloat162float(hi));
        g_cwhi[k*CC + i] = hi; g_cwlo[k*CC + i] = lo;
        s = fmaf(v, v, s);
    }
    red[t] = s;
    __syncthreads();
    for (int st = 64; st > 0; st >>= 1) {
        if (t < st) red[t] += red[t + st];
        __syncthreads();
    }
    if (t == 0) g_c2[k] = red[0];
}

// ---------------- kc_x: transpose + split x -> [b][n][c] bf16 hi/lo ----------------
__global__ __launch_bounds__(256) void kc_x(const float* __restrict__ x) {
    __shared__ float tile[64][33];
    int b = blockIdx.z;
    int c0 = blockIdx.y * 64;
    int n0 = blockIdx.x * 32;
    int t = threadIdx.x;
    const float* xb = x + (size_t)b * CC * NN;

    int nn = t & 31, cg = t >> 5;
    #pragma unroll
    for (int i = 0; i < 8; i++) {
        int cc = cg * 8 + i;
        tile[cc][nn] = xb[(size_t)(c0 + cc) * NN + n0 + nn];
    }
    __syncthreads();
    int pc = t & 31, nr = t >> 5;
    #pragma unroll
    for (int i = 0; i < 4; i++) {
        int n = nr + 8 * i;
        float v0 = tile[pc * 2][n], v1 = tile[pc * 2 + 1][n];
        __nv_bfloat16 h0 = __float2bfloat16(v0), h1 = __float2bfloat16(v1);
        __nv_bfloat16 l0 = __float2bfloat16(v0 - __bfloat162float(h0));
        __nv_bfloat16 l1 = __float2bfloat16(v1 - __bfloat162float(h1));
        size_t idx = ((size_t)b * NN + n0 + n) * (CC/2) + (c0/2) + pc;
        reinterpret_cast<__nv_bfloat162*>(g_xthi)[idx] = __nv_bfloat162(h0, h1);
        reinterpret_cast<__nv_bfloat162*>(g_xtlo)[idx] = __nv_bfloat162(l0, l1);
    }
}

// ---------------- k1_mma: conv GEMM (split bf16) + BN2 + ReLU ----------------
// 3-stage cp.async pipeline. Writes z split bf16 [n][c] only + x2.
static constexpr int TILE16K = 128 * 128;
static constexpr int STAGE = 4 * TILE16K;         // 64KB
static constexpr int SM_K1 = 3 * STAGE;           // 192KB

__global__ __launch_bounds__(256, 1)
void k1_mma(const float* __restrict__ bg, const float* __restrict__ bb_,
            const float* __restrict__ bm, const float* __restrict__ bv)
{
    extern __shared__ char sm[];
    uint32_t sbase = smem_u32(sm);

    int tid = threadIdx.x;
    int lane = tid & 31, wid = tid >> 5;
    int wm = wid & 1, wn = wid >> 1;
    int m0 = blockIdx.x * 128;
    int n0 = blockIdx.y * 128;
    int b  = blockIdx.z;

    int lrow[4], lch[4];
    #pragma unroll
    for (int i = 0; i < 4; i++) {
        int q = tid + 256 * i;
        lrow[i] = q >> 3; lch[i] = q & 7;
    }

    auto load_stage = [&](int ch, int st) {
        uint32_t s0 = sbase + st * STAGE;
        #pragma unroll
        for (int i = 0; i < 4; i++) {
            int row = lrow[i], cc = lch[i];
            uint32_t dst = s0 + SW128((uint32_t)(row * 128 + cc * 16));
            size_t aoff = (size_t)(m0 + row) * CC + ch * 64 + cc * 8;
            size_t boff = ((size_t)b * NN + n0 + row) * CC + ch * 64 + cc * 8;
            CP16(dst,               g_whi + aoff);
            CP16(dst + TILE16K,     g_wlo + aoff);
            CP16(dst + 2*TILE16K,   g_xthi + boff);
            CP16(dst + 3*TILE16K,   g_xtlo + boff);
        }
    };

    float acc[4][4][4];
    #pragma unroll
    for (int mi = 0; mi < 4; mi++)
        #pragma unroll
        for (int nj = 0; nj < 4; nj++)
            #pragma unroll
            for (int r = 0; r < 4; r++) acc[mi][nj][r] = 0.f;

    int rowA = lane & 15, chA = lane >> 4;
    int rowB = ((lane >> 4) << 3) + (lane & 7), chB = (lane >> 3) & 1;

    load_stage(0, 0); CP_COMMIT();
    load_stage(1, 1); CP_COMMIT();

    for (int ch = 0; ch < 8; ch++) {
        if (ch == 7) { CP_WAIT0(); } else { CP_WAIT1(); }
        __syncthreads();
        if (ch < 6) { load_stage(ch + 2, (ch + 2) % 3); CP_COMMIT(); }

        uint32_t s0 = sbase + (ch % 3) * STAGE;
        #pragma unroll
        for (int ks = 0; ks < 4; ks++) {
            uint32_t ahi[4][4], alo[4][4], bhi[2][4], blo[2][4];
            #pragma unroll
            for (int mi = 0; mi < 4; mi++) {
                uint32_t off = SW128((uint32_t)((wm*64 + mi*16 + rowA) * 128 + ks*32 + chA*16));
                ldsm4(s0 + off, ahi[mi]);
                ldsm4(s0 + TILE16K + off, alo[mi]);
            }
            #pragma unroll
            for (int np = 0; np < 2; np++) {
                uint32_t off = SW128((uint32_t)((wn*32 + np*16 + rowB) * 128 + ks*32 + chB*16));
                ldsm4(s0 + 2*TILE16K + off, bhi[np]);
                ldsm4(s0 + 3*TILE16K + off, blo[np]);
            }
            #pragma unroll
            for (int mi = 0; mi < 4; mi++)
                #pragma unroll
                for (int nj = 0; nj < 4; nj++) {
                    const uint32_t* bh = &bhi[nj >> 1][(nj & 1) * 2];
                    const uint32_t* bl = &blo[nj >> 1][(nj & 1) * 2];
                    mma16816(acc[mi][nj], ahi[mi], bh);
                    mma16816(acc[mi][nj], ahi[mi], bl);
                    mma16816(acc[mi][nj], alo[mi], bh);
                }
        }
    }
    __syncthreads();

    // ---- Epilogue: BN2+ReLU; stage split bf16 [n][o]; x2 ----
    __nv_bfloat16* sh_hi = reinterpret_cast<__nv_bfloat16*>(sm);
    __nv_bfloat16* sh_lo = sh_hi + 128 * 136;

    float v2acc[8];
    #pragma unroll
    for (int j = 0; j < 8; j++) v2acc[j] = 0.f;

    #pragma unroll
    for (int mi = 0; mi < 4; mi++) {
        #pragma unroll
        for (int rr = 0; rr < 2; rr++) {
            int o_loc = wm*64 + mi*16 + rr*8 + (lane >> 2);
            int o = m0 + o_loc;
            float sc = bg[o] * rsqrtf(bv[o] + EPSF);
            float sh2 = bb_[o] - bm[o] * sc;
            #pragma unroll
            for (int nj = 0; nj < 4; nj++) {
                float z0 = fmaxf(fmaf(acc[mi][nj][rr*2 + 0], sc, sh2), 0.f);
                float z1 = fmaxf(fmaf(acc[mi][nj][rr*2 + 1], sc, sh2), 0.f);
                v2acc[nj*2 + 0] += z0 * z0;
                v2acc[nj*2 + 1] += z1 * z1;
                __nv_bfloat16 h0 = __float2bfloat16(z0), h1 = __float2bfloat16(z1);
                __nv_bfloat16 l0 = __float2bfloat16(z0 - __bfloat162float(h0));
                __nv_bfloat16 l1 = __float2bfloat16(z1 - __bfloat162float(h1));
                int n_loc = wn*32 + nj*8 + (lane & 3) * 2;
                sh_hi[(n_loc + 0) * 136 + o_loc] = h0;
                sh_hi[(n_loc + 1) * 136 + o_loc] = h1;
                sh_lo[(n_loc + 0) * 136 + o_loc] = l0;
                sh_lo[(n_loc + 1) * 136 + o_loc] = l1;
            }
        }
    }
    #pragma unroll
    for (int j = 0; j < 8; j++) {
        v2acc[j] += __shfl_xor_sync(0xffffffffu, v2acc[j], 4);
        v2acc[j] += __shfl_xor_sync(0xffffffffu, v2acc[j], 8);
        v2acc[j] += __shfl_xor_sync(0xffffffffu, v2acc[j], 16);
    }
    if ((lane >> 2) == 0) {
        #pragma unroll
        for (int j = 0; j < 8; j++) {
            int n_loc = wn*32 + (j >> 1) * 8 + (lane & 3) * 2 + (j & 1);
            atomicAdd(&g_x2[b*NN + n0 + n_loc], v2acc[j]);
        }
    }
    __syncthreads();
    #pragma unroll
    for (int i = 0; i < 8; i++) {
        int idx = tid + 256 * i;
        int row = idx >> 4, c16 = idx & 15;
        uint4 vh = *reinterpret_cast<const uint4*>(sh_hi + row * 136 + c16 * 8);
        uint4 vl = *reinterpret_cast<const uint4*>(sh_lo + row * 136 + c16 * 8);
        size_t di = ((size_t)b*NN + n0 + row) * CC + m0 + c16 * 8;
        *reinterpret_cast<uint4*>(&g_znhi[di]) = vh;
        *reinterpret_cast<uint4*>(&g_znlo[di]) = vl;
    }
}

// ---------------- k2_mma: assignment via tensor cores + fused softmax ----------------
static constexpr int K2_CW_HI = 0;
static constexpr int K2_CW_LO = 32768;
static constexpr int K2_ZST   = 65536;          // 2 stages x 64KB
static constexpr int K2_X2S   = 196608;
static constexpr int K2_ASUM  = 197632;
static constexpr int SM_K2    = 197760;

__global__ __launch_bounds__(256, 1)
void k2_mma(const float* __restrict__ scale)
{
    extern __shared__ char sm[];
    uint32_t sbase = smem_u32(sm);
    int tid = threadIdx.x, lane = tid & 31, w = tid >> 5;
    int b = blockIdx.y;
    int n0 = blockIdx.x * 256;
    int q = lane >> 2;

    if (tid < 32) *reinterpret_cast<float*>(sm + K2_ASUM + tid*4) = 0.f;
    const uint4* cwh4 = reinterpret_cast<const uint4*>(g_cwhi);
    const uint4* cwl4 = reinterpret_cast<const uint4*>(g_cwlo);
    #pragma unroll
    for (int i = 0; i < 8; i++) {
        int idx = tid + 256 * i;
        int row = idx >> 6, cb = idx & 63;
        uint32_t off = (uint32_t)(row * 1024 + ((cb * 16) ^ ((row & 7) << 4)));
        *reinterpret_cast<uint4*>(sm + K2_CW_HI + off) = cwh4[row * 64 + cb];
        *reinterpret_cast<uint4*>(sm + K2_CW_LO + off) = cwl4[row * 64 + cb];
    }
    *reinterpret_cast<float*>(sm + K2_X2S + tid*4) = g_x2[b*NN + n0 + tid];

    auto load_z = [&](int ch, int st) {
        uint32_t s0 = sbase + K2_ZST + st * 65536;
        #pragma unroll
        for (int i = 0; i < 8; i++) {
            int idx = tid + 256 * i;
            int row = idx >> 3, col = idx & 7;
            uint32_t dst = s0 + SW128((uint32_t)(row * 128 + col * 16));
            size_t src = ((size_t)b*NN + n0 + row) * CC + ch * 64 + col * 8;
            CP16(dst,         g_znhi + src);
            CP16(dst + 32768, g_znlo + src);
        }
    };

    float acc[2][4][4];
    #pragma unroll
    for (int mf = 0; mf < 2; mf++)
        #pragma unroll
        for (int nj = 0; nj < 4; nj++)
            #pragma unroll
            for (int r = 0; r < 4; r++) acc[mf][nj][r] = 0.f;

    load_z(0, 0);
    CP_COMMIT();

    for (int ch = 0; ch < 8; ch++) {
        CP_WAIT0();
        __syncthreads();
        if (ch < 7) { load_z(ch + 1, (ch + 1) & 1); CP_COMMIT(); }
        uint32_t zs = sbase + K2_ZST + (ch & 1) * 65536;
        #pragma unroll
        for (int ks = 0; ks < 4; ks++) {
            uint32_t ah[2][4], al[2][4], bh[2][4], bl[2][4];
            #pragma unroll
            for (int mf = 0; mf < 2; mf++) {
                int code = mf * 16 + (lane & 15);
                uint32_t off = (uint32_t)(code * 1024 +
                    ((ch*128 + ks*32 + (lane >> 4) * 16) ^ ((code & 7) << 4)));
                ldsm4(sbase + K2_CW_HI + off, ah[mf]);
                ldsm4(sbase + K2_CW_LO + off, al[mf]);
            }
            #pragma unroll
            for (int p = 0; p < 2; p++) {
                int row = w*32 + p*16 + ((lane >> 4) << 3) + (lane & 7);
                uint32_t off = SW128((uint32_t)(row * 128 + ks*32 + ((lane >> 3) & 1) * 16));
                ldsm4(zs + off, bh[p]);
                ldsm4(zs + off + 32768, bl[p]);
            }
            #pragma unroll
            for (int mf = 0; mf < 2; mf++)
                #pragma unroll
                for (int nj = 0; nj < 4; nj++) {
                    const uint32_t* Bh = &bh[nj >> 1][(nj & 1) * 2];
                    const uint32_t* Bl = &bl[nj >> 1][(nj & 1) * 2];
                    mma16816(acc[mf][nj], ah[mf], Bh);
                    mma16816(acc[mf][nj], ah[mf], Bl);
                    mma16816(acc[mf][nj], al[mf], Bh);
                }
        }
        __syncthreads();
    }

    // ---- softmax over codes (m axis) ----
    float s4[4], c24[4];
    #pragma unroll
    for (int ci = 0; ci < 4; ci++) {
        s4[ci] = __ldg(&scale[q + 8*ci]);
        c24[ci] = g_c2[q + 8*ci];
    }
    float l[4][8];
    #pragma unroll
    for (int mf = 0; mf < 2; mf++)
        #pragma unroll
        for (int nj = 0; nj < 4; nj++)
            #pragma unroll
            for (int r = 0; r < 4; r++) {
                int ci = mf*2 + (r >> 1);
                int j  = nj*2 + (r & 1);
                int col = nj*8 + (lane & 3)*2 + (r & 1);
                float x2v = *reinterpret_cast<const float*>(sm + K2_X2S + (w*32 + col)*4);
                l[ci][j] = s4[ci] * (x2v - 2.f * acc[mf][nj][r] + c24[ci]);
            }
    float mx[8], sme[8], inv[8];
    #pragma unroll
    for (int j = 0; j < 8; j++) {
        mx[j] = fmaxf(fmaxf(l[0][j], l[1][j]), fmaxf(l[2][j], l[3][j]));
        mx[j] = fmaxf(mx[j], __shfl_xor_sync(0xffffffffu, mx[j], 4));
        mx[j] = fmaxf(mx[j], __shfl_xor_sync(0xffffffffu, mx[j], 8));
        mx[j] = fmaxf(mx[j], __shfl_xor_sync(0xffffffffu, mx[j], 16));
    }
    #pragma unroll
    for (int j = 0; j < 8; j++) {
        sme[j] = 0.f;
        #pragma unroll
        for (int ci = 0; ci < 4; ci++) {
            float e = __expf(l[ci][j] - mx[j]);
            l[ci][j] = e; sme[j] += e;
        }
        sme[j] += __shfl_xor_sync(0xffffffffu, sme[j], 4);
        sme[j] += __shfl_xor_sync(0xffffffffu, sme[j], 8);
        sme[j] += __shfl_xor_sync(0xffffffffu, sme[j], 16);
        inv[j] = 1.f / sme[j];
    }
    __nv_bfloat16* as_hi = reinterpret_cast<__nv_bfloat16*>(sm + K2_ZST);
    __nv_bfloat16* as_lo = as_hi + 32 * 256;
    float apart[4];
    #pragma unroll
    for (int ci = 0; ci < 4; ci++) apart[ci] = 0.f;
    #pragma unroll
    for (int ci = 0; ci < 4; ci++)
        #pragma unroll
        for (int j = 0; j < 8; j++) {
            float av = l[ci][j] * inv[j];
            apart[ci] += av;
            int code = q + 8*ci;
            int pix = w*32 + (j >> 1)*8 + (lane & 3)*2 + (j & 1);
            __nv_bfloat16 hv = __float2bfloat16(av);
            __nv_bfloat16 lv = __float2bfloat16(av - __bfloat162float(hv));
            as_hi[code*256 + pix] = hv;
            as_lo[code*256 + pix] = lv;
        }
    #pragma unroll
    for (int ci = 0; ci < 4; ci++) {
        apart[ci] += __shfl_xor_sync(0xffffffffu, apart[ci], 1);
        apart[ci] += __shfl_xor_sync(0xffffffffu, apart[ci], 2);
    }
    if ((lane & 3) == 0) {
        #pragma unroll
        for (int ci = 0; ci < 4; ci++)
            atomicAdd(reinterpret_cast<float*>(sm + K2_ASUM + (q + 8*ci)*4), apart[ci]);
    }
    __syncthreads();
    #pragma unroll
    for (int i = 0; i < 4; i++) {
        int idx = tid + 256 * i;
        int row = idx >> 5, c16 = idx & 31;
        size_t di = ((size_t)(b*KCODE + row)) * NN + n0 + c16 * 8;
        *reinterpret_cast<uint4*>(&g_ashi[di]) = *reinterpret_cast<const uint4*>(as_hi + idx*8);
        *reinterpret_cast<uint4*>(&g_aslo[di]) = *reinterpret_cast<const uint4*>(as_lo + idx*8);
    }
    if (tid < 32)
        atomicAdd(&g_asum[b*KCODE + tid], *reinterpret_cast<float*>(sm + K2_ASUM + tid*4));
}

// ---------------- k3_mma: agg via tensor cores ----------------
// C[c][codes], A = z from [n][c] buffer via ldmatrix.trans, B = assign[k][n].
// 3-stage pipeline; atomicAdd into aggT[b][c][k].
static constexpr int K3_STG = 73728;   // z_hi 32K | z_lo 32K | a_hi 4K | a_lo 4K
static constexpr int SM_K3 = 3 * K3_STG;   // 216KB

__global__ __launch_bounds__(256, 1)
void k3_mma()
{
    extern __shared__ char sm[];
    uint32_t sbase = smem_u32(sm);
    int tid = threadIdx.x, lane = tid & 31, w = tid >> 5;
    int c0 = blockIdx.x * 256;
    int pbase = blockIdx.y * 1024;
    int b = blockIdx.z;

    auto load = [&](int chunk, int st) {
        uint32_t s0 = sbase + st * K3_STG;
        int pix = pbase + chunk * 64;
        // z tile [64 n][256 c] hi/lo, 512B rows, row-xor swizzle
        #pragma unroll
        for (int i = 0; i < 8; i++) {
            int idx = tid + 256 * i;
            int row = idx >> 5, col16 = idx & 31;
            uint32_t byte = (uint32_t)(row * 512 + col16 * 16);
            uint32_t sw = byte ^ (((uint32_t)row & 7) << 4);
            size_t src = ((size_t)b*NN + pix + row) * CC + c0 + col16 * 8;
            CP16(s0 + sw,         g_znhi + src);
            CP16(s0 + 32768 + sw, g_znlo + src);
        }
        // assign tile [32 k][64 n], 128B rows, SW128
        {
            int row = tid >> 3, col = tid & 7;
            uint32_t dst = s0 + 65536 + SW128((uint32_t)(row * 128 + col * 16));
            size_t src = ((size_t)(b*KCODE + row)) * NN + pix + col * 8;
            CP16(dst,        g_ashi + src);
            CP16(dst + 4096, g_aslo + src);
        }
    };

    float acc[2][4][4];
    #pragma unroll
    for (int mf = 0; mf < 2; mf++)
        #pragma unroll
        for (int nj = 0; nj < 4; nj++)
            #pragma unroll
            for (int r = 0; r < 4; r++) acc[mf][nj][r] = 0.f;

    load(0, 0); CP_COMMIT();
    load(1, 1); CP_COMMIT();

    for (int chunk = 0; chunk < 16; chunk++) {
        if (chunk == 15) { CP_WAIT0(); } else { CP_WAIT1(); }
        __syncthreads();
        if (chunk < 14) { load(chunk + 2, (chunk + 2) % 3); CP_COMMIT(); }
        uint32_t s0 = sbase + (chunk % 3) * K3_STG;
        #pragma unroll
        for (int ks = 0; ks < 4; ks++) {
            uint32_t zh[2][4], zl[2][4], ah[2][4], al[2][4];
            // A via trans ldmatrix: lanes address [n][c] storage
            int n_row = ks*16 + ((lane >> 4) << 3) + (lane & 7);
            #pragma unroll
            for (int mf = 0; mf < 2; mf++) {
                int c_col = w*32 + mf*16 + ((lane >> 3) & 1) * 8;
                uint32_t byte = (uint32_t)(n_row * 512 + c_col * 2);
                uint32_t sw = byte ^ (((uint32_t)n_row & 7) << 4);
                ldsm4t(s0 + sw, zh[mf]);
                ldsm4t(s0 + 32768 + sw, zl[mf]);
            }
            #pragma unroll
            for (int p = 0; p < 2; p++) {
                int row = p*16 + ((lane >> 4) << 3) + (lane & 7);
                uint32_t off = SW128((uint32_t)(row * 128 + ks*32 + ((lane >> 3) & 1) * 16));
                ldsm4(s0 + 65536 + off, ah[p]);
                ldsm4(s0 + 69632 + off, al[p]);
            }
            #pragma unroll
            for (int mf = 0; mf < 2; mf++)
                #pragma unroll
                for (int nj = 0; nj < 4; nj++) {
                    const uint32_t* Bh = &ah[nj >> 1][(nj & 1) * 2];
                    const uint32_t* Bl = &al[nj >> 1][(nj & 1) * 2];
                    mma16816(acc[mf][nj], zh[mf], Bh);
                    mma16816(acc[mf][nj], zh[mf], Bl);
                    mma16816(acc[mf][nj], zl[mf], Bh);
                }
        }
    }

    #pragma unroll
    for (int mf = 0; mf < 2; mf++)
        #pragma unroll
        for (int nj = 0; nj < 4; nj++)
            #pragma unroll
            for (int r = 0; r < 4; r++) {
                int c = c0 + w*32 + mf*16 + (lane >> 2) + (r >> 1) * 8;
                int k = nj*8 + (lane & 3)*2 + (r & 1);
                atomicAdd(&g_aggT[((size_t)b*CC + c)*KCODE + k], acc[mf][nj][r]);
            }
}

// ---------------- k4a / k4b / k5 ----------------
__global__ void k4a_feat(
    const float* __restrict__ cw,
    const float* __restrict__ g1, const float* __restrict__ b1,
    const float* __restrict__ m1, const float* __restrict__ v1,
    float* __restrict__ out_feat)
{
    int b = blockIdx.x;
    int c = threadIdx.x;
    float f = 0.f;
    #pragma unroll
    for (int k = 0; k < KCODE; k++) {
        float a = g_aggT[((size_t)b*CC + c)*KCODE + k] - g_asum[b*KCODE + k] * cw[k*CC + c];
        float s = g1[k] * rsqrtf(v1[k] + EPSF);
        float e = fmaxf(fmaf(a - m1[k], s, b1[k]), 0.f);
        f += e;
    }
    f *= (1.f / KCODE);
    g_feat[b*CC + c] = f;
    out_feat[b*CC + c] = f;
}

__global__ void k4b_gamma(const float* __restrict__ fw, const float* __restrict__ fb) {
    __shared__ float fs[CC];
    int b = blockIdx.x;
    int o = threadIdx.x;
    fs[o] = g_feat[b*CC + o];
    __syncthreads();
    float acc = fb[o];
    const float* row = fw + (size_t)o * CC;
    #pragma unroll 8
    for (int c = 0; c < CC; c++) acc = fmaf(fs[c], row[c], acc);
    g_gamma[b*CC + o] = 1.f / (1.f + __expf(-acc));
}

__global__ void k5_gate(const float* __restrict__ x, float* __restrict__ out) {
    int i = blockIdx.x * blockDim.x + threadIdx.x;
    const int total4 = BB * CC * NN / 4;
    if (i >= total4) return;
    int bc = (i * 4) / NN;
    float g = 1.f + g_gamma[bc];
    float4 xv = reinterpret_cast<const float4*>(x)[i];
    float4 o;
    o.x = fmaxf(xv.x * g, 0.f);
    o.y = fmaxf(xv.y * g, 0.f);
    o.z = fmaxf(xv.z * g, 0.f);
    o.w = fmaxf(xv.w * g, 0.f);
    reinterpret_cast<float4*>(out)[i] = o;
}

// ---------------- launch ----------------
extern "C" void kernel_launch(void* const* d_in, const int* in_sizes, int n_in,
                              void* d_out, int out_size) {
    const float* x      = (const float*)d_in[0];
    const float* conv_w = (const float*)d_in[1];
    const float* bn2_g  = (const float*)d_in[2];
    const float* bn2_b  = (const float*)d_in[3];
    const float* bn2_m  = (const float*)d_in[4];
    const float* bn2_v  = (const float*)d_in[5];
    const float* cw     = (const float*)d_in[6];
    const float* scale  = (const float*)d_in[7];
    const float* bn1_g  = (const float*)d_in[8];
    const float* bn1_b  = (const float*)d_in[9];
    const float* bn1_m  = (const float*)d_in[10];
    const float* bn1_v  = (const float*)d_in[11];
    const float* fc_w   = (const float*)d_in[12];
    const float* fc_b   = (const float*)d_in[13];
    float* out = (float*)d_out;

    cudaFuncSetAttribute(k1_mma, cudaFuncAttributeMaxDynamicSharedMemorySize, SM_K1);
    cudaFuncSetAttribute(k2_mma, cudaFuncAttributeMaxDynamicSharedMemorySize, SM_K2);
    cudaFuncSetAttribute(k3_mma, cudaFuncAttributeMaxDynamicSharedMemorySize, SM_K3);

    k0_zero<<<128, 256>>>();
    kc_w<<<(CC*CC + 255) / 256, 256>>>(conv_w);
    kc_cw<<<KCODE, 128>>>(cw);
    kc_x<<<dim3(NN / 32, CC / 64, BB), 256>>>(x);
    k1_mma<<<dim3(CC / 128, NN / 128, BB), 256, SM_K1>>>(bn2_g, bn2_b, bn2_m, bn2_v);
    k2_mma<<<dim3(NN / 256, BB), 256, SM_K2>>>(scale);
    k3_mma<<<dim3(CC / 256, NN / 1024, BB), 256, SM_K3>>>();
    k4a_feat<<<BB, CC>>>(cw, bn1_g, bn1_b, bn1_m, bn1_v, out);
    k4b_gamma<<<BB, CC>>>(fc_w, fc_b);
    k5_gate<<<(BB * CC * NN / 4 + 255) / 256, 256>>>(x, out + BB * CC);
}

// round 6
// speedup vs baseline: 1.9831x; 1.0035x over previous
#include <cuda_runtime.h>
#include <cuda_bf16.h>
#include <cstdint>

#define BB 4
#define CC 512
#define HH 128
#define WW 128
#define NN (HH*WW)      // 16384
#define KCODE 32
#define EPSF 1e-5f

// ---------------- device scratch ----------------
__device__ float g_x2[BB*NN];                               // sum_c z^2 per pixel
__device__ float g_asum[BB*KCODE];
__device__ float g_aggT[BB*CC*KCODE];                       // agg transposed [b][c][k]
__device__ float g_feat[BB*CC];
__device__ float g_gamma[BB*CC];
__device__ float g_c2[KCODE];
__device__ __align__(256) __nv_bfloat16 g_whi[CC*CC];       // conv_w split [o][c]
__device__ __align__(256) __nv_bfloat16 g_wlo[CC*CC];
__device__ __align__(256) __nv_bfloat16 g_cwhi[KCODE*CC];   // codewords split [k][c]
__device__ __align__(256) __nv_bfloat16 g_cwlo[KCODE*CC];
__device__ __align__(256) __nv_bfloat16 g_xthi[(size_t)BB*NN*CC]; // x transposed+split [b][n][c]
__device__ __align__(256) __nv_bfloat16 g_xtlo[(size_t)BB*NN*CC];
__device__ __align__(256) __nv_bfloat16 g_znhi[(size_t)BB*NN*CC]; // z split [b][n][c]
__device__ __align__(256) __nv_bfloat16 g_znlo[(size_t)BB*NN*CC];

// ---------------- helpers ----------------
__device__ __forceinline__ uint32_t smem_u32(const void* p) {
    uint32_t a;
    asm("{ .reg .u64 t; cvta.to.shared.u64 t, %1; cvt.u32.u64 %0, t; }" : "=r"(a) : "l"(p));
    return a;
}
#define SW128(off) ((off) ^ (((off) >> 3) & 0x70))
#define CP16(dst, src) asm volatile("cp.async.cg.shared.global [%0], [%1], 16;" \
    :: "r"(dst), "l"(__cvta_generic_to_global(src)) : "memory")
#define CP_COMMIT() asm volatile("cp.async.commit_group;" ::: "memory")
#define CP_WAIT0()  asm volatile("cp.async.wait_group 0;" ::: "memory")
#define CP_WAIT1()  asm volatile("cp.async.wait_group 1;" ::: "memory")

__device__ __forceinline__ void ldsm4(uint32_t addr, uint32_t* r) {
    asm volatile("ldmatrix.sync.aligned.m8n8.x4.shared.b16 {%0,%1,%2,%3}, [%4];"
        : "=r"(r[0]), "=r"(r[1]), "=r"(r[2]), "=r"(r[3]) : "r"(addr));
}
__device__ __forceinline__ void ldsm4t(uint32_t addr, uint32_t* r) {
    asm volatile("ldmatrix.sync.aligned.m8n8.x4.trans.shared.b16 {%0,%1,%2,%3}, [%4];"
        : "=r"(r[0]), "=r"(r[1]), "=r"(r[2]), "=r"(r[3]) : "r"(addr));
}
__device__ __forceinline__ void mma16816(float* c, const uint32_t* a, const uint32_t* b) {
    asm volatile("mma.sync.aligned.m16n8k16.row.col.f32.bf16.bf16.f32 "
        "{%0,%1,%2,%3}, {%4,%5,%6,%7}, {%8,%9}, {%0,%1,%2,%3};"
        : "+f"(c[0]), "+f"(c[1]), "+f"(c[2]), "+f"(c[3])
        : "r"(a[0]), "r"(a[1]), "r"(a[2]), "r"(a[3]), "r"(b[0]), "r"(b[1]));
}

// ---------------- k0: zero accumulated buffers ----------------
__global__ void k0_zero() {
    int i = blockIdx.x * blockDim.x + threadIdx.x;
    int stride = gridDim.x * blockDim.x;
    for (int j = i; j < BB*CC*KCODE; j += stride) g_aggT[j] = 0.f;
    for (int j = i; j < BB*NN; j += stride) g_x2[j] = 0.f;
    if (i < BB*KCODE) g_asum[i] = 0.f;
}

// ---------------- kc_w: split conv_w into bf16 hi/lo ----------------
__global__ void kc_w(const float* __restrict__ w) {
    int i = blockIdx.x * blockDim.x + threadIdx.x;
    if (i >= CC*CC) return;
    float v = w[i];
    __nv_bfloat16 hi = __float2bfloat16(v);
    __nv_bfloat16 lo = __float2bfloat16(v - __bfloat162float(hi));
    g_whi[i] = hi; g_wlo[i] = lo;
}

// ---------------- kc_cw: split codewords + c2 ----------------
__global__ void kc_cw(const float* __restrict__ cw) {
    __shared__ float red[128];
    int k = blockIdx.x, t = threadIdx.x;
    float s = 0.f;
    for (int i = t; i < CC; i += 128) {
        float v = cw[k*CC + i];
        __nv_bfloat16 hi = __float2bfloat16(v);
        __nv_bfloat16 lo = __float2bfloat16(v - __bfloat162float(hi));
        g_cwhi[k*CC + i] = hi; g_cwlo[k*CC + i] = lo;
        s = fmaf(v, v, s);
    }
    red[t] = s;
    __syncthreads();
    for (int st = 64; st > 0; st >>= 1) {
        if (t < st) red[t] += red[t + st];
        __syncthreads();
    }
    if (t == 0) g_c2[k] = red[0];
}

// ---------------- kc_x: transpose + split x -> [b][n][c] bf16 hi/lo ----------------
__global__ __launch_bounds__(256) void kc_x(const float* __restrict__ x) {
    __shared__ float tile[64][33];
    int b = blockIdx.z;
    int c0 = blockIdx.y * 64;
    int n0 = blockIdx.x * 32;
    int t = threadIdx.x;
    const float* xb = x + (size_t)b * CC * NN;

    int nn = t & 31, cg = t >> 5;
    #pragma unroll
    for (int i = 0; i < 8; i++) {
        int cc = cg * 8 + i;
        tile[cc][nn] = xb[(size_t)(c0 + cc) * NN + n0 + nn];
    }
    __syncthreads();
    int pc = t & 31, nr = t >> 5;
    #pragma unroll
    for (int i = 0; i < 4; i++) {
        int n = nr + 8 * i;
        float v0 = tile[pc * 2][n], v1 = tile[pc * 2 + 1][n];
        __nv_bfloat16 h0 = __float2bfloat16(v0), h1 = __float2bfloat16(v1);
        __nv_bfloat16 l0 = __float2bfloat16(v0 - __bfloat162float(h0));
        __nv_bfloat16 l1 = __float2bfloat16(v1 - __bfloat162float(h1));
        size_t idx = ((size_t)b * NN + n0 + n) * (CC/2) + (c0/2) + pc;
        reinterpret_cast<__nv_bfloat162*>(g_xthi)[idx] = __nv_bfloat162(h0, h1);
        reinterpret_cast<__nv_bfloat162*>(g_xtlo)[idx] = __nv_bfloat162(l0, l1);
    }
}

// ---------------- k1_mma: conv GEMM (split bf16) + BN2 + ReLU ----------------
static constexpr int TILE16K = 128 * 128;
static constexpr int STAGE = 4 * TILE16K;         // 64KB
static constexpr int SM_K1 = 3 * STAGE;           // 192KB

__global__ __launch_bounds__(256, 1)
void k1_mma(const float* __restrict__ bg, const float* __restrict__ bb_,
            const float* __restrict__ bm, const float* __restrict__ bv)
{
    extern __shared__ char sm[];
    uint32_t sbase = smem_u32(sm);

    int tid = threadIdx.x;
    int lane = tid & 31, wid = tid >> 5;
    int wm = wid & 1, wn = wid >> 1;
    int m0 = blockIdx.x * 128;
    int n0 = blockIdx.y * 128;
    int b  = blockIdx.z;

    int lrow[4], lch[4];
    #pragma unroll
    for (int i = 0; i < 4; i++) {
        int q = tid + 256 * i;
        lrow[i] = q >> 3; lch[i] = q & 7;
    }

    auto load_stage = [&](int ch, int st) {
        uint32_t s0 = sbase + st * STAGE;
        #pragma unroll
        for (int i = 0; i < 4; i++) {
            int row = lrow[i], cc = lch[i];
            uint32_t dst = s0 + SW128((uint32_t)(row * 128 + cc * 16));
            size_t aoff = (size_t)(m0 + row) * CC + ch * 64 + cc * 8;
            size_t boff = ((size_t)b * NN + n0 + row) * CC + ch * 64 + cc * 8;
            CP16(dst,               g_whi + aoff);
            CP16(dst + TILE16K,     g_wlo + aoff);
            CP16(dst + 2*TILE16K,   g_xthi + boff);
            CP16(dst + 3*TILE16K,   g_xtlo + boff);
        }
    };

    float acc[4][4][4];
    #pragma unroll
    for (int mi = 0; mi < 4; mi++)
        #pragma unroll
        for (int nj = 0; nj < 4; nj++)
            #pragma unroll
            for (int r = 0; r < 4; r++) acc[mi][nj][r] = 0.f;

    int rowA = lane & 15, chA = lane >> 4;
    int rowB = ((lane >> 4) << 3) + (lane & 7), chB = (lane >> 3) & 1;

    load_stage(0, 0); CP_COMMIT();
    load_stage(1, 1); CP_COMMIT();

    for (int ch = 0; ch < 8; ch++) {
        if (ch == 7) { CP_WAIT0(); } else { CP_WAIT1(); }
        __syncthreads();
        if (ch < 6) { load_stage(ch + 2, (ch + 2) % 3); CP_COMMIT(); }

        uint32_t s0 = sbase + (ch % 3) * STAGE;
        #pragma unroll
        for (int ks = 0; ks < 4; ks++) {
            uint32_t ahi[4][4], alo[4][4], bhi[2][4], blo[2][4];
            #pragma unroll
            for (int mi = 0; mi < 4; mi++) {
                uint32_t off = SW128((uint32_t)((wm*64 + mi*16 + rowA) * 128 + ks*32 + chA*16));
                ldsm4(s0 + off, ahi[mi]);
                ldsm4(s0 + TILE16K + off, alo[mi]);
            }
            #pragma unroll
            for (int np = 0; np < 2; np++) {
                uint32_t off = SW128((uint32_t)((wn*32 + np*16 + rowB) * 128 + ks*32 + chB*16));
                ldsm4(s0 + 2*TILE16K + off, bhi[np]);
                ldsm4(s0 + 3*TILE16K + off, blo[np]);
            }
            #pragma unroll
            for (int mi = 0; mi < 4; mi++)
                #pragma unroll
                for (int nj = 0; nj < 4; nj++) {
                    const uint32_t* bh = &bhi[nj >> 1][(nj & 1) * 2];
                    const uint32_t* bl = &blo[nj >> 1][(nj & 1) * 2];
                    mma16816(acc[mi][nj], ahi[mi], bh);
                    mma16816(acc[mi][nj], ahi[mi], bl);
                    mma16816(acc[mi][nj], alo[mi], bh);
                }
        }
    }
    __syncthreads();

    // ---- Epilogue: BN2+ReLU; stage split bf16 [n][o]; x2 ----
    __nv_bfloat16* sh_hi = reinterpret_cast<__nv_bfloat16*>(sm);
    __nv_bfloat16* sh_lo = sh_hi + 128 * 136;

    float v2acc[8];
    #pragma unroll
    for (int j = 0; j < 8; j++) v2acc[j] = 0.f;

    #pragma unroll
    for (int mi = 0; mi < 4; mi++) {
        #pragma unroll
        for (int rr = 0; rr < 2; rr++) {
            int o_loc = wm*64 + mi*16 + rr*8 + (lane >> 2);
            int o = m0 + o_loc;
            float sc = bg[o] * rsqrtf(bv[o] + EPSF);
            float sh2 = bb_[o] - bm[o] * sc;
            #pragma unroll
            for (int nj = 0; nj < 4; nj++) {
                float z0 = fmaxf(fmaf(acc[mi][nj][rr*2 + 0], sc, sh2), 0.f);
                float z1 = fmaxf(fmaf(acc[mi][nj][rr*2 + 1], sc, sh2), 0.f);
                v2acc[nj*2 + 0] += z0 * z0;
                v2acc[nj*2 + 1] += z1 * z1;
                __nv_bfloat16 h0 = __float2bfloat16(z0), h1 = __float2bfloat16(z1);
                __nv_bfloat16 l0 = __float2bfloat16(z0 - __bfloat162float(h0));
                __nv_bfloat16 l1 = __float2bfloat16(z1 - __bfloat162float(h1));
                int n_loc = wn*32 + nj*8 + (lane & 3) * 2;
                sh_hi[(n_loc + 0) * 136 + o_loc] = h0;
                sh_hi[(n_loc + 1) * 136 + o_loc] = h1;
                sh_lo[(n_loc + 0) * 136 + o_loc] = l0;
                sh_lo[(n_loc + 1) * 136 + o_loc] = l1;
            }
        }
    }
    #pragma unroll
    for (int j = 0; j < 8; j++) {
        v2acc[j] += __shfl_xor_sync(0xffffffffu, v2acc[j], 4);
        v2acc[j] += __shfl_xor_sync(0xffffffffu, v2acc[j], 8);
        v2acc[j] += __shfl_xor_sync(0xffffffffu, v2acc[j], 16);
    }
    if ((lane >> 2) == 0) {
        #pragma unroll
        for (int j = 0; j < 8; j++) {
            int n_loc = wn*32 + (j >> 1) * 8 + (lane & 3) * 2 + (j & 1);
            atomicAdd(&g_x2[b*NN + n0 + n_loc], v2acc[j]);
        }
    }
    __syncthreads();
    #pragma unroll
    for (int i = 0; i < 8; i++) {
        int idx = tid + 256 * i;
        int row = idx >> 4, c16 = idx & 15;
        uint4 vh = *reinterpret_cast<const uint4*>(sh_hi + row * 136 + c16 * 8);
        uint4 vl = *reinterpret_cast<const uint4*>(sh_lo + row * 136 + c16 * 8);
        size_t di = ((size_t)b*NN + n0 + row) * CC + m0 + c16 * 8;
        *reinterpret_cast<uint4*>(&g_znhi[di]) = vh;
        *reinterpret_cast<uint4*>(&g_znlo[di]) = vl;
    }
}

// ---------------- k23_mma: fused assignment + aggregation ----------------
// Phase 1: C[codes 32][pixels 256] = cw @ z^T, softmax -> assign (smem) + asum.
// Phase 2: aggT[c][k] += z[n][c]^T-frags @ assign, streaming the (L2-hot) z
// tiles again through a 3-stage pipeline; atomicAdd flush per c-chunk.
static constexpr int K2_CW_HI = 0;          // phase1 cw; phase2 z-stage buf 0
static constexpr int K2_CW_LO = 32768;
static constexpr int K2_ZST   = 65536;      // phase1 z double buffer (2 x 64KB)
static constexpr int K2_X2S   = 196608;     // 1KB
static constexpr int K2_ASUM  = 197632;     // 128B
static constexpr int K2_ASG   = 197760;     // assign hi 16KB | lo 16KB
static constexpr int SM_K23   = 230528;

__global__ __launch_bounds__(256, 1)
void k23_mma(const float* __restrict__ scale)
{
    extern __shared__ char sm[];
    uint32_t sbase = smem_u32(sm);
    int tid = threadIdx.x, lane = tid & 31, w = tid >> 5;
    int b = blockIdx.y;
    int n0 = blockIdx.x * 256;
    int q = lane >> 2;

    if (tid < 32) *reinterpret_cast<float*>(sm + K2_ASUM + tid*4) = 0.f;
    const uint4* cwh4 = reinterpret_cast<const uint4*>(g_cwhi);
    const uint4* cwl4 = reinterpret_cast<const uint4*>(g_cwlo);
    #pragma unroll
    for (int i = 0; i < 8; i++) {
        int idx = tid + 256 * i;
        int row = idx >> 6, cb = idx & 63;
        uint32_t off = (uint32_t)(row * 1024 + ((cb * 16) ^ ((row & 7) << 4)));
        *reinterpret_cast<uint4*>(sm + K2_CW_HI + off) = cwh4[row * 64 + cb];
        *reinterpret_cast<uint4*>(sm + K2_CW_LO + off) = cwl4[row * 64 + cb];
    }
    *reinterpret_cast<float*>(sm + K2_X2S + tid*4) = g_x2[b*NN + n0 + tid];

    // z tile loader: [256 n rows][64 c] hi/lo, 128B rows, SW128. base = byte offset.
    auto load_z = [&](int ch, uint32_t base) {
        uint32_t s0 = sbase + base;
        #pragma unroll
        for (int i = 0; i < 8; i++) {
            int idx = tid + 256 * i;
            int row = idx >> 3, col = idx & 7;
            uint32_t dst = s0 + SW128((uint32_t)(row * 128 + col * 16));
            size_t src = ((size_t)b*NN + n0 + row) * CC + ch * 64 + col * 8;
            CP16(dst,         g_znhi + src);
            CP16(dst + 32768, g_znlo + src);
        }
    };

    float acc[2][4][4];
    #pragma unroll
    for (int mf = 0; mf < 2; mf++)
        #pragma unroll
        for (int nj = 0; nj < 4; nj++)
            #pragma unroll
            for (int r = 0; r < 4; r++) acc[mf][nj][r] = 0.f;

    load_z(0, K2_ZST);
    CP_COMMIT();

    // ---- Phase 1: xc GEMM ----
    for (int ch = 0; ch < 8; ch++) {
        CP_WAIT0();
        __syncthreads();
        if (ch < 7) { load_z(ch + 1, K2_ZST + ((ch + 1) & 1) * 65536); CP_COMMIT(); }
        uint32_t zs = sbase + K2_ZST + (ch & 1) * 65536;
        #pragma unroll
        for (int ks = 0; ks < 4; ks++) {
            uint32_t ah[2][4], al[2][4], bh[2][4], bl[2][4];
            #pragma unroll
            for (int mf = 0; mf < 2; mf++) {
                int code = mf * 16 + (lane & 15);
                uint32_t off = (uint32_t)(code * 1024 +
                    ((ch*128 + ks*32 + (lane >> 4) * 16) ^ ((code & 7) << 4)));
                ldsm4(sbase + K2_CW_HI + off, ah[mf]);
                ldsm4(sbase + K2_CW_LO + off, al[mf]);
            }
            #pragma unroll
            for (int p = 0; p < 2; p++) {
                int row = w*32 + p*16 + ((lane >> 4) << 3) + (lane & 7);
                uint32_t off = SW128((uint32_t)(row * 128 + ks*32 + ((lane >> 3) & 1) * 16));
                ldsm4(zs + off, bh[p]);
                ldsm4(zs + off + 32768, bl[p]);
            }
            #pragma unroll
            for (int mf = 0; mf < 2; mf++)
                #pragma unroll
                for (int nj = 0; nj < 4; nj++) {
                    const uint32_t* Bh = &bh[nj >> 1][(nj & 1) * 2];
                    const uint32_t* Bl = &bl[nj >> 1][(nj & 1) * 2];
                    mma16816(acc[mf][nj], ah[mf], Bh);
                    mma16816(acc[mf][nj], ah[mf], Bl);
                    mma16816(acc[mf][nj], al[mf], Bh);
                }
        }
        __syncthreads();
    }

    // prefetch phase-2 chunks 0,1 (cw region + phase1 buf 0 are now free)
    load_z(0, 0);     CP_COMMIT();
    load_z(1, 65536); CP_COMMIT();

    // ---- softmax over codes (m axis) ----
    float s4[4], c24[4];
    #pragma unroll
    for (int ci = 0; ci < 4; ci++) {
        s4[ci] = __ldg(&scale[q + 8*ci]);
        c24[ci] = g_c2[q + 8*ci];
    }
    float l[4][8];
    #pragma unroll
    for (int mf = 0; mf < 2; mf++)
        #pragma unroll
        for (int nj = 0; nj < 4; nj++)
            #pragma unroll
            for (int r = 0; r < 4; r++) {
                int ci = mf*2 + (r >> 1);
                int j  = nj*2 + (r & 1);
                int col = nj*8 + (lane & 3)*2 + (r & 1);
                float x2v = *reinterpret_cast<const float*>(sm + K2_X2S + (w*32 + col)*4);
                l[ci][j] = s4[ci] * (x2v - 2.f * acc[mf][nj][r] + c24[ci]);
            }
    float mx[8], sme[8], inv[8];
    #pragma unroll
    for (int j = 0; j < 8; j++) {
        mx[j] = fmaxf(fmaxf(l[0][j], l[1][j]), fmaxf(l[2][j], l[3][j]));
        mx[j] = fmaxf(mx[j], __shfl_xor_sync(0xffffffffu, mx[j], 4));
        mx[j] = fmaxf(mx[j], __shfl_xor_sync(0xffffffffu, mx[j], 8));
        mx[j] = fmaxf(mx[j], __shfl_xor_sync(0xffffffffu, mx[j], 16));
    }
    #pragma unroll
    for (int j = 0; j < 8; j++) {
        sme[j] = 0.f;
        #pragma unroll
        for (int ci = 0; ci < 4; ci++) {
            float e = __expf(l[ci][j] - mx[j]);
            l[ci][j] = e; sme[j] += e;
        }
        sme[j] += __shfl_xor_sync(0xffffffffu, sme[j], 4);
        sme[j] += __shfl_xor_sync(0xffffffffu, sme[j], 8);
        sme[j] += __shfl_xor_sync(0xffffffffu, sme[j], 16);
        inv[j] = 1.f / sme[j];
    }
    // assign -> smem [code][pix], 512B rows, 16B-chunk xor swizzle; + asum
    float apart[4];
    #pragma unroll
    for (int ci = 0; ci < 4; ci++) apart[ci] = 0.f;
    #pragma unroll
    for (int ci = 0; ci < 4; ci++)
        #pragma unroll
        for (int j = 0; j < 8; j++) {
            float av = l[ci][j] * inv[j];
            apart[ci] += av;
            int code = q + 8*ci;
            int pix = w*32 + (j >> 1)*8 + (lane & 3)*2 + (j & 1);
            __nv_bfloat16 hv = __float2bfloat16(av);
            __nv_bfloat16 lv = __float2bfloat16(av - __bfloat162float(hv));
            uint32_t aoff = (uint32_t)(code*512) +
                ((((uint32_t)pix >> 3) ^ (uint32_t)(code & 7)) << 4) + ((uint32_t)pix & 7) * 2;
            *reinterpret_cast<__nv_bfloat16*>(sm + K2_ASG + aoff) = hv;
            *reinterpret_cast<__nv_bfloat16*>(sm + K2_ASG + 16384 + aoff) = lv;
        }
    #pragma unroll
    for (int ci = 0; ci < 4; ci++) {
        apart[ci] += __shfl_xor_sync(0xffffffffu, apart[ci], 1);
        apart[ci] += __shfl_xor_sync(0xffffffffu, apart[ci], 2);
    }
    if ((lane & 3) == 0) {
        #pragma unroll
        for (int ci = 0; ci < 4; ci++)
            atomicAdd(reinterpret_cast<float*>(sm + K2_ASUM + (q + 8*ci)*4), apart[ci]);
    }
    __syncthreads();
    if (tid < 32)
        atomicAdd(&g_asum[b*KCODE + tid], *reinterpret_cast<float*>(sm + K2_ASUM + tid*4));

    // ---- Phase 2: aggT partials for this pixel slab ----
    // Per chunk ch2 (c range ch2*64..+64): C[c 64][k 32] over n=256.
    // Warp w: m-frag (w>>1), codes half (w&1).
    for (int ch2 = 0; ch2 < 8; ch2++) {
        if (ch2 == 7) { CP_WAIT0(); } else { CP_WAIT1(); }
        __syncthreads();
        if (ch2 < 6) { load_z(ch2 + 2, ((ch2 + 2) % 3) * 65536); CP_COMMIT(); }
        uint32_t s0 = sbase + (ch2 % 3) * 65536;

        float acc2[2][4];
        #pragma unroll
        for (int j = 0; j < 2; j++)
            #pragma unroll
            for (int r = 0; r < 4; r++) acc2[j][r] = 0.f;

        #pragma unroll
        for (int ks = 0; ks < 16; ks++) {
            uint32_t Ah[4], Al[4], Bh[4], Bl[4];
            int n_row = ks*16 + ((lane >> 4) << 3) + (lane & 7);
            int c_col = (w >> 1)*16 + ((lane >> 3) & 1) * 8;
            uint32_t abyte = SW128((uint32_t)(n_row * 128 + c_col * 2));
            ldsm4t(s0 + abyte, Ah);
            ldsm4t(s0 + 32768 + abyte, Al);
            int code_row = (w & 1)*16 + ((lane >> 4) << 3) + (lane & 7);
            uint32_t ch16 = (uint32_t)(ks*2 + ((lane >> 3) & 1));
            uint32_t bbyte = (uint32_t)(code_row * 512) +
                ((ch16 ^ (uint32_t)(code_row & 7)) << 4);
            ldsm4(sbase + K2_ASG + bbyte, Bh);
            ldsm4(sbase + K2_ASG + 16384 + bbyte, Bl);
            #pragma unroll
            for (int j = 0; j < 2; j++) {
                mma16816(acc2[j], Ah, &Bh[j*2]);
                mma16816(acc2[j], Ah, &Bl[j*2]);
                mma16816(acc2[j], Al, &Bh[j*2]);
            }
        }
        #pragma unroll
        for (int j = 0; j < 2; j++)
            #pragma unroll
            for (int r = 0; r < 4; r++) {
                int c = ch2*64 + (w >> 1)*16 + (lane >> 2) + (r >> 1) * 8;
                int k = (w & 1)*16 + j*8 + (lane & 3)*2 + (r & 1);
                atomicAdd(&g_aggT[((size_t)b*CC + c)*KCODE + k], acc2[j][r]);
            }
    }
}

// ---------------- k4a / k4b / k5 ----------------
__global__ void k4a_feat(
    const float* __restrict__ cw,
    const float* __restrict__ g1, const float* __restrict__ b1,
    const float* __restrict__ m1, const float* __restrict__ v1,
    float* __restrict__ out_feat)
{
    int b = blockIdx.x;
    int c = threadIdx.x;
    float f = 0.f;
    #pragma unroll
    for (int k = 0; k < KCODE; k++) {
        float a = g_aggT[((size_t)b*CC + c)*KCODE + k] - g_asum[b*KCODE + k] * cw[k*CC + c];
        float s = g1[k] * rsqrtf(v1[k] + EPSF);
        float e = fmaxf(fmaf(a - m1[k], s, b1[k]), 0.f);
        f += e;
    }
    f *= (1.f / KCODE);
    g_feat[b*CC + c] = f;
    out_feat[b*CC + c] = f;
}

__global__ void k4b_gamma(const float* __restrict__ fw, const float* __restrict__ fb) {
    __shared__ float fs[CC];
    int b = blockIdx.x;
    int o = threadIdx.x;
    fs[o] = g_feat[b*CC + o];
    __syncthreads();
    float acc = fb[o];
    const float* row = fw + (size_t)o * CC;
    #pragma unroll 8
    for (int c = 0; c < CC; c++) acc = fmaf(fs[c], row[c], acc);
    g_gamma[b*CC + o] = 1.f / (1.f + __expf(-acc));
}

__global__ void k5_gate(const float* __restrict__ x, float* __restrict__ out) {
    int i = blockIdx.x * blockDim.x + threadIdx.x;
    const int total4 = BB * CC * NN / 4;
    if (i >= total4) return;
    int bc = (i * 4) / NN;
    float g = 1.f + g_gamma[bc];
    float4 xv = reinterpret_cast<const float4*>(x)[i];
    float4 o;
    o.x = fmaxf(xv.x * g, 0.f);
    o.y = fmaxf(xv.y * g, 0.f);
    o.z = fmaxf(xv.z * g, 0.f);
    o.w = fmaxf(xv.w * g, 0.f);
    reinterpret_cast<float4*>(out)[i] = o;
}

// ---------------- launch ----------------
extern "C" void kernel_launch(void* const* d_in, const int* in_sizes, int n_in,
                              void* d_out, int out_size) {
    const float* x      = (const float*)d_in[0];
    const float* conv_w = (const float*)d_in[1];
    const float* bn2_g  = (const float*)d_in[2];
    const float* bn2_b  = (const float*)d_in[3];
    const float* bn2_m  = (const float*)d_in[4];
    const float* bn2_v  = (const float*)d_in[5];
    const float* cw     = (const float*)d_in[6];
    const float* scale  = (const float*)d_in[7];
    const float* bn1_g  = (const float*)d_in[8];
    const float* bn1_b  = (const float*)d_in[9];
    const float* bn1_m  = (const float*)d_in[10];
    const float* bn1_v  = (const float*)d_in[11];
    const float* fc_w   = (const float*)d_in[12];
    const float* fc_b   = (const float*)d_in[13];
    float* out = (float*)d_out;

    cudaFuncSetAttribute(k1_mma, cudaFuncAttributeMaxDynamicSharedMemorySize, SM_K1);
    cudaFuncSetAttribute(k23_mma, cudaFuncAttributeMaxDynamicSharedMemorySize, SM_K23);

    k0_zero<<<128, 256>>>();
    kc_w<<<(CC*CC + 255) / 256, 256>>>(conv_w);
    kc_cw<<<KCODE, 128>>>(cw);
    kc_x<<<dim3(NN / 32, CC / 64, BB), 256>>>(x);
    k1_mma<<<dim3(CC / 128, NN / 128, BB), 256, SM_K1>>>(bn2_g, bn2_b, bn2_m, bn2_v);
    k23_mma<<<dim3(NN / 256, BB), 256, SM_K23>>>(scale);
    k4a_feat<<<BB, CC>>>(cw, bn1_g, bn1_b, bn1_m, bn1_v, out);
    k4b_gamma<<<BB, CC>>>(fc_w, fc_b);
    k5_gate<<<(BB * CC * NN / 4 + 255) / 256, 256>>>(x, out + BB * CC);
}

// round 7
// speedup vs baseline: 2.0495x; 1.0335x over previous
#include <cuda_runtime.h>
#include <cuda_bf16.h>
#include <cstdint>

#define BB 4
#define CC 512
#define HH 128
#define WW 128
#define NN (HH*WW)      // 16384
#define KCODE 32
#define EPSF 1e-5f

// ---------------- device scratch ----------------
__device__ float g_x2[BB*NN];                               // sum_c z^2 per pixel
__device__ float g_asum[BB*KCODE];
__device__ float g_aggT[BB*CC*KCODE];                       // agg transposed [b][c][k]
__device__ float g_feat[BB*CC];
__device__ float g_gamma[BB*CC];
__device__ float g_c2[KCODE];
__device__ __align__(256) __nv_bfloat16 g_whi[CC*CC];       // conv_w split [o][c]
__device__ __align__(256) __nv_bfloat16 g_wlo[CC*CC];
__device__ __align__(256) __nv_bfloat16 g_cwhi[KCODE*CC];   // codewords split [k][c]
__device__ __align__(256) __nv_bfloat16 g_cwlo[KCODE*CC];
__device__ __align__(256) __nv_bfloat16 g_xthi[(size_t)BB*NN*CC]; // x transposed+split [b][n][c]
__device__ __align__(256) __nv_bfloat16 g_xtlo[(size_t)BB*NN*CC];
__device__ __align__(256) __nv_bfloat16 g_znhi[(size_t)BB*NN*CC]; // z split [b][n][c]
__device__ __align__(256) __nv_bfloat16 g_znlo[(size_t)BB*NN*CC];

// ---------------- helpers ----------------
__device__ __forceinline__ uint32_t smem_u32(const void* p) {
    uint32_t a;
    asm("{ .reg .u64 t; cvta.to.shared.u64 t, %1; cvt.u32.u64 %0, t; }" : "=r"(a) : "l"(p));
    return a;
}
#define SW128(off) ((off) ^ (((off) >> 3) & 0x70))
#define CP16(dst, src) asm volatile("cp.async.cg.shared.global [%0], [%1], 16;" \
    :: "r"(dst), "l"(__cvta_generic_to_global(src)) : "memory")
#define CP_COMMIT() asm volatile("cp.async.commit_group;" ::: "memory")
#define CP_WAIT0()  asm volatile("cp.async.wait_group 0;" ::: "memory")
#define CP_WAIT1()  asm volatile("cp.async.wait_group 1;" ::: "memory")

__device__ __forceinline__ void ldsm4(uint32_t addr, uint32_t* r) {
    asm volatile("ldmatrix.sync.aligned.m8n8.x4.shared.b16 {%0,%1,%2,%3}, [%4];"
        : "=r"(r[0]), "=r"(r[1]), "=r"(r[2]), "=r"(r[3]) : "r"(addr));
}
__device__ __forceinline__ void ldsm4t(uint32_t addr, uint32_t* r) {
    asm volatile("ldmatrix.sync.aligned.m8n8.x4.trans.shared.b16 {%0,%1,%2,%3}, [%4];"
        : "=r"(r[0]), "=r"(r[1]), "=r"(r[2]), "=r"(r[3]) : "r"(addr));
}
__device__ __forceinline__ void mma16816(float* c, const uint32_t* a, const uint32_t* b) {
    asm volatile("mma.sync.aligned.m16n8k16.row.col.f32.bf16.bf16.f32 "
        "{%0,%1,%2,%3}, {%4,%5,%6,%7}, {%8,%9}, {%0,%1,%2,%3};"
        : "+f"(c[0]), "+f"(c[1]), "+f"(c[2]), "+f"(c[3])
        : "r"(a[0]), "r"(a[1]), "r"(a[2]), "r"(a[3]), "r"(b[0]), "r"(b[1]));
}

// ---------------- k0: zero accumulated buffers ----------------
__global__ void k0_zero() {
    int i = blockIdx.x * blockDim.x + threadIdx.x;
    int stride = gridDim.x * blockDim.x;
    for (int j = i; j < BB*CC*KCODE; j += stride) g_aggT[j] = 0.f;
    for (int j = i; j < BB*NN; j += stride) g_x2[j] = 0.f;
    if (i < BB*KCODE) g_asum[i] = 0.f;
}

// ---------------- kc_w: split conv_w into bf16 hi/lo ----------------
__global__ void kc_w(const float* __restrict__ w) {
    int i = blockIdx.x * blockDim.x + threadIdx.x;
    if (i >= CC*CC) return;
    float v = w[i];
    __nv_bfloat16 hi = __float2bfloat16(v);
    __nv_bfloat16 lo = __float2bfloat16(v - __bfloat162float(hi));
    g_whi[i] = hi; g_wlo[i] = lo;
}

// ---------------- kc_cw: split codewords + c2 ----------------
__global__ void kc_cw(const float* __restrict__ cw) {
    __shared__ float red[128];
    int k = blockIdx.x, t = threadIdx.x;
    float s = 0.f;
    for (int i = t; i < CC; i += 128) {
        float v = cw[k*CC + i];
        __nv_bfloat16 hi = __float2bfloat16(v);
        __nv_bfloat16 lo = __float2bfloat16(v - __bfloat162float(hi));
        g_cwhi[k*CC + i] = hi; g_cwlo[k*CC + i] = lo;
        s = fmaf(v, v, s);
    }
    red[t] = s;
    __syncthreads();
    for (int st = 64; st > 0; st >>= 1) {
        if (t < st) red[t] += red[t + st];
        __syncthreads();
    }
    if (t == 0) g_c2[k] = red[0];
}

// ---------------- kc_x: transpose + split x -> [b][n][c] bf16 hi/lo ----------------
__global__ __launch_bounds__(256) void kc_x(const float* __restrict__ x) {
    __shared__ float tile[64][33];
    int b = blockIdx.z;
    int c0 = blockIdx.y * 64;
    int n0 = blockIdx.x * 32;
    int t = threadIdx.x;
    const float* xb = x + (size_t)b * CC * NN;

    int nn = t & 31, cg = t >> 5;
    #pragma unroll
    for (int i = 0; i < 8; i++) {
        int cc = cg * 8 + i;
        tile[cc][nn] = xb[(size_t)(c0 + cc) * NN + n0 + nn];
    }
    __syncthreads();
    int pc = t & 31, nr = t >> 5;
    #pragma unroll
    for (int i = 0; i < 4; i++) {
        int n = nr + 8 * i;
        float v0 = tile[pc * 2][n], v1 = tile[pc * 2 + 1][n];
        __nv_bfloat16 h0 = __float2bfloat16(v0), h1 = __float2bfloat16(v1);
        __nv_bfloat16 l0 = __float2bfloat16(v0 - __bfloat162float(h0));
        __nv_bfloat16 l1 = __float2bfloat16(v1 - __bfloat162float(h1));
        size_t idx = ((size_t)b * NN + n0 + n) * (CC/2) + (c0/2) + pc;
        reinterpret_cast<__nv_bfloat162*>(g_xthi)[idx] = __nv_bfloat162(h0, h1);
        reinterpret_cast<__nv_bfloat162*>(g_xtlo)[idx] = __nv_bfloat162(l0, l1);
    }
}

// ---------------- k1_mma: conv GEMM (split bf16) + BN2 + ReLU ----------------
// Block 128(M=o) x 256(N=n), BK=64, 8 warps in 2(m) x 4(n), warp tile 64x64.
// Stage: A_hi 16K | A_lo 16K | B_hi 32K | B_lo 32K = 96KB, 2 stages = 192KB.
static constexpr int K1_STAGE = 98304;
static constexpr int SM_K1 = 2 * K1_STAGE;        // 192KB

__global__ __launch_bounds__(256, 1)
void k1_mma(const float* __restrict__ bg, const float* __restrict__ bb_,
            const float* __restrict__ bm, const float* __restrict__ bv)
{
    extern __shared__ char sm[];
    uint32_t sbase = smem_u32(sm);

    int tid = threadIdx.x;
    int lane = tid & 31, wid = tid >> 5;
    int wm = wid & 1, wn = wid >> 1;             // warp tile: rows wm*64, cols wn*64
    int m0 = blockIdx.x * 128;
    int n0 = blockIdx.y * 256;
    int b  = blockIdx.z;

    auto load_stage = [&](int ch, int st) {
        uint32_t s0 = sbase + st * K1_STAGE;
        #pragma unroll
        for (int i = 0; i < 4; i++) {           // A: 128 rows x 8 chunks16
            int idx = tid + 256 * i;
            int row = idx >> 3, cc8 = idx & 7;
            uint32_t dst = s0 + SW128((uint32_t)(row * 128 + cc8 * 16));
            size_t aoff = (size_t)(m0 + row) * CC + ch * 64 + cc8 * 8;
            CP16(dst,          g_whi + aoff);
            CP16(dst + 16384,  g_wlo + aoff);
        }
        #pragma unroll
        for (int i = 0; i < 8; i++) {           // B: 256 rows x 8 chunks16
            int idx = tid + 256 * i;
            int row = idx >> 3, cc8 = idx & 7;
            uint32_t dst = s0 + 32768 + SW128((uint32_t)(row * 128 + cc8 * 16));
            size_t boff = ((size_t)b * NN + n0 + row) * CC + ch * 64 + cc8 * 8;
            CP16(dst,          g_xthi + boff);
            CP16(dst + 32768,  g_xtlo + boff);
        }
    };

    float acc[4][8][4];
    #pragma unroll
    for (int mi = 0; mi < 4; mi++)
        #pragma unroll
        for (int nj = 0; nj < 8; nj++)
            #pragma unroll
            for (int r = 0; r < 4; r++) acc[mi][nj][r] = 0.f;

    int rowA = lane & 15, chA = lane >> 4;
    int rowB = ((lane >> 4) << 3) + (lane & 7), chB = (lane >> 3) & 1;

    load_stage(0, 0); CP_COMMIT();

    for (int ch = 0; ch < 8; ch++) {
        CP_WAIT0();
        __syncthreads();
        if (ch < 7) { load_stage(ch + 1, (ch + 1) & 1); CP_COMMIT(); }

        uint32_t s0 = sbase + (ch & 1) * K1_STAGE;
        #pragma unroll
        for (int ks = 0; ks < 4; ks++) {
            uint32_t ahi[4][4], alo[4][4], bhi[4][4], blo[4][4];
            #pragma unroll
            for (int mi = 0; mi < 4; mi++) {
                uint32_t off = SW128((uint32_t)((wm*64 + mi*16 + rowA) * 128 + ks*32 + chA*16));
                ldsm4(s0 + off, ahi[mi]);
                ldsm4(s0 + 16384 + off, alo[mi]);
            }
            #pragma unroll
            for (int np = 0; np < 4; np++) {
                uint32_t off = 32768 + SW128((uint32_t)((wn*64 + np*16 + rowB) * 128 + ks*32 + chB*16));
                ldsm4(s0 + off, bhi[np]);
                ldsm4(s0 + 32768 + off, blo[np]);
            }
            #pragma unroll
            for (int mi = 0; mi < 4; mi++)
                #pragma unroll
                for (int nj = 0; nj < 8; nj++) {
                    const uint32_t* bh = &bhi[nj >> 1][(nj & 1) * 2];
                    const uint32_t* bl = &blo[nj >> 1][(nj & 1) * 2];
                    mma16816(acc[mi][nj], ahi[mi], bh);
                    mma16816(acc[mi][nj], ahi[mi], bl);
                    mma16816(acc[mi][nj], alo[mi], bh);
                }
        }
    }
    __syncthreads();

    // ---- Epilogue: BN2+ReLU; stage split bf16 [n 256][o 128]; x2 ----
    __nv_bfloat16* sh_hi = reinterpret_cast<__nv_bfloat16*>(sm);
    __nv_bfloat16* sh_lo = sh_hi + 256 * 136;

    float v2acc[16];
    #pragma unroll
    for (int j = 0; j < 16; j++) v2acc[j] = 0.f;

    #pragma unroll
    for (int mi = 0; mi < 4; mi++) {
        #pragma unroll
        for (int rr = 0; rr < 2; rr++) {
            int o_loc = wm*64 + mi*16 + rr*8 + (lane >> 2);
            int o = m0 + o_loc;
            float sc = bg[o] * rsqrtf(bv[o] + EPSF);
            float sh2 = bb_[o] - bm[o] * sc;
            #pragma unroll
            for (int nj = 0; nj < 8; nj++) {
                float z0 = fmaxf(fmaf(acc[mi][nj][rr*2 + 0], sc, sh2), 0.f);
                float z1 = fmaxf(fmaf(acc[mi][nj][rr*2 + 1], sc, sh2), 0.f);
                v2acc[nj*2 + 0] += z0 * z0;
                v2acc[nj*2 + 1] += z1 * z1;
                __nv_bfloat16 h0 = __float2bfloat16(z0), h1 = __float2bfloat16(z1);
                __nv_bfloat16 l0 = __float2bfloat16(z0 - __bfloat162float(h0));
                __nv_bfloat16 l1 = __float2bfloat16(z1 - __bfloat162float(h1));
                int n_loc = wn*64 + nj*8 + (lane & 3) * 2;
                sh_hi[(n_loc + 0) * 136 + o_loc] = h0;
                sh_hi[(n_loc + 1) * 136 + o_loc] = h1;
                sh_lo[(n_loc + 0) * 136 + o_loc] = l0;
                sh_lo[(n_loc + 1) * 136 + o_loc] = l1;
            }
        }
    }
    #pragma unroll
    for (int j = 0; j < 16; j++) {
        v2acc[j] += __shfl_xor_sync(0xffffffffu, v2acc[j], 4);
        v2acc[j] += __shfl_xor_sync(0xffffffffu, v2acc[j], 8);
        v2acc[j] += __shfl_xor_sync(0xffffffffu, v2acc[j], 16);
    }
    if ((lane >> 2) == 0) {      // lanes 0-3, only wm==0 warps contribute? no: both wm rows summed separately
        #pragma unroll
        for (int j = 0; j < 16; j++) {
            int n_loc = wn*64 + (j >> 1) * 8 + (lane & 3) * 2 + (j & 1);
            atomicAdd(&g_x2[b*NN + n0 + n_loc], v2acc[j]);
        }
    }
    __syncthreads();
    #pragma unroll
    for (int i = 0; i < 16; i++) {
        int idx = tid + 256 * i;
        int row = idx >> 4, c16 = idx & 15;
        uint4 vh = *reinterpret_cast<const uint4*>(sh_hi + row * 136 + c16 * 8);
        uint4 vl = *reinterpret_cast<const uint4*>(sh_lo + row * 136 + c16 * 8);
        size_t di = ((size_t)b*NN + n0 + row) * CC + m0 + c16 * 8;
        *reinterpret_cast<uint4*>(&g_znhi[di]) = vh;
        *reinterpret_cast<uint4*>(&g_znlo[di]) = vl;
    }
}

// ---------------- k23_mma: fused assignment + aggregation ----------------
static constexpr int K2_CW_HI = 0;          // phase1 cw; phase2 z-stage buf 0
static constexpr int K2_CW_LO = 32768;
static constexpr int K2_ZST   = 65536;      // phase1 z double buffer (2 x 64KB)
static constexpr int K2_X2S   = 196608;     // 1KB
static constexpr int K2_ASUM  = 197632;     // 128B
static constexpr int K2_ASG   = 197760;     // assign hi 16KB | lo 16KB
static constexpr int SM_K23   = 230528;

__global__ __launch_bounds__(256, 1)
void k23_mma(const float* __restrict__ scale)
{
    extern __shared__ char sm[];
    uint32_t sbase = smem_u32(sm);
    int tid = threadIdx.x, lane = tid & 31, w = tid >> 5;
    int b = blockIdx.y;
    int n0 = blockIdx.x * 256;
    int q = lane >> 2;

    if (tid < 32) *reinterpret_cast<float*>(sm + K2_ASUM + tid*4) = 0.f;
    const uint4* cwh4 = reinterpret_cast<const uint4*>(g_cwhi);
    const uint4* cwl4 = reinterpret_cast<const uint4*>(g_cwlo);
    #pragma unroll
    for (int i = 0; i < 8; i++) {
        int idx = tid + 256 * i;
        int row = idx >> 6, cb = idx & 63;
        uint32_t off = (uint32_t)(row * 1024 + ((cb * 16) ^ ((row & 7) << 4)));
        *reinterpret_cast<uint4*>(sm + K2_CW_HI + off) = cwh4[row * 64 + cb];
        *reinterpret_cast<uint4*>(sm + K2_CW_LO + off) = cwl4[row * 64 + cb];
    }
    *reinterpret_cast<float*>(sm + K2_X2S + tid*4) = g_x2[b*NN + n0 + tid];

    auto load_z = [&](int ch, uint32_t base) {
        uint32_t s0 = sbase + base;
        #pragma unroll
        for (int i = 0; i < 8; i++) {
            int idx = tid + 256 * i;
            int row = idx >> 3, col = idx & 7;
            uint32_t dst = s0 + SW128((uint32_t)(row * 128 + col * 16));
            size_t src = ((size_t)b*NN + n0 + row) * CC + ch * 64 + col * 8;
            CP16(dst,         g_znhi + src);
            CP16(dst + 32768, g_znlo + src);
        }
    };

    float acc[2][4][4];
    #pragma unroll
    for (int mf = 0; mf < 2; mf++)
        #pragma unroll
        for (int nj = 0; nj < 4; nj++)
            #pragma unroll
            for (int r = 0; r < 4; r++) acc[mf][nj][r] = 0.f;

    load_z(0, K2_ZST);
    CP_COMMIT();

    // ---- Phase 1: xc GEMM ----
    for (int ch = 0; ch < 8; ch++) {
        CP_WAIT0();
        __syncthreads();
        if (ch < 7) { load_z(ch + 1, K2_ZST + ((ch + 1) & 1) * 65536); CP_COMMIT(); }
        uint32_t zs = sbase + K2_ZST + (ch & 1) * 65536;
        #pragma unroll
        for (int ks = 0; ks < 4; ks++) {
            uint32_t ah[2][4], al[2][4], bh[2][4], bl[2][4];
            #pragma unroll
            for (int mf = 0; mf < 2; mf++) {
                int code = mf * 16 + (lane & 15);
                uint32_t off = (uint32_t)(code * 1024 +
                    ((ch*128 + ks*32 + (lane >> 4) * 16) ^ ((code & 7) << 4)));
                ldsm4(sbase + K2_CW_HI + off, ah[mf]);
                ldsm4(sbase + K2_CW_LO + off, al[mf]);
            }
            #pragma unroll
            for (int p = 0; p < 2; p++) {
                int row = w*32 + p*16 + ((lane >> 4) << 3) + (lane & 7);
                uint32_t off = SW128((uint32_t)(row * 128 + ks*32 + ((lane >> 3) & 1) * 16));
                ldsm4(zs + off, bh[p]);
                ldsm4(zs + off + 32768, bl[p]);
            }
            #pragma unroll
            for (int mf = 0; mf < 2; mf++)
                #pragma unroll
                for (int nj = 0; nj < 4; nj++) {
                    const uint32_t* Bh = &bh[nj >> 1][(nj & 1) * 2];
                    const uint32_t* Bl = &bl[nj >> 1][(nj & 1) * 2];
                    mma16816(acc[mf][nj], ah[mf], Bh);
                    mma16816(acc[mf][nj], ah[mf], Bl);
                    mma16816(acc[mf][nj], al[mf], Bh);
                }
        }
        __syncthreads();
    }

    // prefetch phase-2 chunks 0,1 (cw region + phase1 buf 0 are now free)
    load_z(0, 0);     CP_COMMIT();
    load_z(1, 65536); CP_COMMIT();

    // ---- softmax over codes (m axis) ----
    float s4[4], c24[4];
    #pragma unroll
    for (int ci = 0; ci < 4; ci++) {
        s4[ci] = __ldg(&scale[q + 8*ci]);
        c24[ci] = g_c2[q + 8*ci];
    }
    float l[4][8];
    #pragma unroll
    for (int mf = 0; mf < 2; mf++)
        #pragma unroll
        for (int nj = 0; nj < 4; nj++)
            #pragma unroll
            for (int r = 0; r < 4; r++) {
                int ci = mf*2 + (r >> 1);
                int j  = nj*2 + (r & 1);
                int col = nj*8 + (lane & 3)*2 + (r & 1);
                float x2v = *reinterpret_cast<const float*>(sm + K2_X2S + (w*32 + col)*4);
                l[ci][j] = s4[ci] * (x2v - 2.f * acc[mf][nj][r] + c24[ci]);
            }
    float mx[8], sme[8], inv[8];
    #pragma unroll
    for (int j = 0; j < 8; j++) {
        mx[j] = fmaxf(fmaxf(l[0][j], l[1][j]), fmaxf(l[2][j], l[3][j]));
        mx[j] = fmaxf(mx[j], __shfl_xor_sync(0xffffffffu, mx[j], 4));
        mx[j] = fmaxf(mx[j], __shfl_xor_sync(0xffffffffu, mx[j], 8));
        mx[j] = fmaxf(mx[j], __shfl_xor_sync(0xffffffffu, mx[j], 16));
    }
    #pragma unroll
    for (int j = 0; j < 8; j++) {
        sme[j] = 0.f;
        #pragma unroll
        for (int ci = 0; ci < 4; ci++) {
            float e = __expf(l[ci][j] - mx[j]);
            l[ci][j] = e; sme[j] += e;
        }
        sme[j] += __shfl_xor_sync(0xffffffffu, sme[j], 4);
        sme[j] += __shfl_xor_sync(0xffffffffu, sme[j], 8);
        sme[j] += __shfl_xor_sync(0xffffffffu, sme[j], 16);
        inv[j] = 1.f / sme[j];
    }
    float apart[4];
    #pragma unroll
    for (int ci = 0; ci < 4; ci++) apart[ci] = 0.f;
    #pragma unroll
    for (int ci = 0; ci < 4; ci++)
        #pragma unroll
        for (int j = 0; j < 8; j++) {
            float av = l[ci][j] * inv[j];
            apart[ci] += av;
            int code = q + 8*ci;
            int pix = w*32 + (j >> 1)*8 + (lane & 3)*2 + (j & 1);
            __nv_bfloat16 hv = __float2bfloat16(av);
            __nv_bfloat16 lv = __float2bfloat16(av - __bfloat162float(hv));
            uint32_t aoff = (uint32_t)(code*512) +
                ((((uint32_t)pix >> 3) ^ (uint32_t)(code & 7)) << 4) + ((uint32_t)pix & 7) * 2;
            *reinterpret_cast<__nv_bfloat16*>(sm + K2_ASG + aoff) = hv;
            *reinterpret_cast<__nv_bfloat16*>(sm + K2_ASG + 16384 + aoff) = lv;
        }
    #pragma unroll
    for (int ci = 0; ci < 4; ci++) {
        apart[ci] += __shfl_xor_sync(0xffffffffu, apart[ci], 1);
        apart[ci] += __shfl_xor_sync(0xffffffffu, apart[ci], 2);
    }
    if ((lane & 3) == 0) {
        #pragma unroll
        for (int ci = 0; ci < 4; ci++)
            atomicAdd(reinterpret_cast<float*>(sm + K2_ASUM + (q + 8*ci)*4), apart[ci]);
    }
    __syncthreads();
    if (tid < 32)
        atomicAdd(&g_asum[b*KCODE + tid], *reinterpret_cast<float*>(sm + K2_ASUM + tid*4));

    // ---- Phase 2: aggT partials for this pixel slab ----
    for (int ch2 = 0; ch2 < 8; ch2++) {
        if (ch2 == 7) { CP_WAIT0(); } else { CP_WAIT1(); }
        __syncthreads();
        if (ch2 < 6) { load_z(ch2 + 2, ((ch2 + 2) % 3) * 65536); CP_COMMIT(); }
        uint32_t s0 = sbase + (ch2 % 3) * 65536;

        float acc2[2][4];
        #pragma unroll
        for (int j = 0; j < 2; j++)
            #pragma unroll
            for (int r = 0; r < 4; r++) acc2[j][r] = 0.f;

        #pragma unroll
        for (int ks = 0; ks < 16; ks++) {
            uint32_t Ah[4], Al[4], Bh[4], Bl[4];
            int n_row = ks*16 + ((lane >> 4) << 3) + (lane & 7);
            int c_col = (w >> 1)*16 + ((lane >> 3) & 1) * 8;
            uint32_t abyte = SW128((uint32_t)(n_row * 128 + c_col * 2));
            ldsm4t(s0 + abyte, Ah);
            ldsm4t(s0 + 32768 + abyte, Al);
            int code_row = (w & 1)*16 + ((lane >> 4) << 3) + (lane & 7);
            uint32_t ch16 = (uint32_t)(ks*2 + ((lane >> 3) & 1));
            uint32_t bbyte = (uint32_t)(code_row * 512) +
                ((ch16 ^ (uint32_t)(code_row & 7)) << 4);
            ldsm4(sbase + K2_ASG + bbyte, Bh);
            ldsm4(sbase + K2_ASG + 16384 + bbyte, Bl);
            #pragma unroll
            for (int j = 0; j < 2; j++) {
                mma16816(acc2[j], Ah, &Bh[j*2]);
                mma16816(acc2[j], Ah, &Bl[j*2]);
                mma16816(acc2[j], Al, &Bh[j*2]);
            }
        }
        #pragma unroll
        for (int j = 0; j < 2; j++)
            #pragma unroll
            for (int r = 0; r < 4; r++) {
                int c = ch2*64 + (w >> 1)*16 + (lane >> 2) + (r >> 1) * 8;
                int k = (w & 1)*16 + j*8 + (lane & 3)*2 + (r & 1);
                atomicAdd(&g_aggT[((size_t)b*CC + c)*KCODE + k], acc2[j][r]);
            }
    }
}

// ---------------- k4a / k4b / k5 ----------------
__global__ void k4a_feat(
    const float* __restrict__ cw,
    const float* __restrict__ g1, const float* __restrict__ b1,
    const float* __restrict__ m1, const float* __restrict__ v1,
    float* __restrict__ out_feat)
{
    int b = blockIdx.x;
    int c = threadIdx.x;
    float f = 0.f;
    #pragma unroll
    for (int k = 0; k < KCODE; k++) {
        float a = g_aggT[((size_t)b*CC + c)*KCODE + k] - g_asum[b*KCODE + k] * cw[k*CC + c];
        float s = g1[k] * rsqrtf(v1[k] + EPSF);
        float e = fmaxf(fmaf(a - m1[k], s, b1[k]), 0.f);
        f += e;
    }
    f *= (1.f / KCODE);
    g_feat[b*CC + c] = f;
    out_feat[b*CC + c] = f;
}

__global__ void k4b_gamma(const float* __restrict__ fw, const float* __restrict__ fb) {
    __shared__ float fs[CC];
    int b = blockIdx.x;
    int o = threadIdx.x;
    fs[o] = g_feat[b*CC + o];
    __syncthreads();
    float acc = fb[o];
    const float* row = fw + (size_t)o * CC;
    #pragma unroll 8
    for (int c = 0; c < CC; c++) acc = fmaf(fs[c], row[c], acc);
    g_gamma[b*CC + o] = 1.f / (1.f + __expf(-acc));
}

__global__ void k5_gate(const float* __restrict__ x, float* __restrict__ out) {
    int i = blockIdx.x * blockDim.x + threadIdx.x;
    const int total4 = BB * CC * NN / 4;
    if (i >= total4) return;
    int bc = (i * 4) / NN;
    float g = 1.f + g_gamma[bc];
    float4 xv = reinterpret_cast<const float4*>(x)[i];
    float4 o;
    o.x = fmaxf(xv.x * g, 0.f);
    o.y = fmaxf(xv.y * g, 0.f);
    o.z = fmaxf(xv.z * g, 0.f);
    o.w = fmaxf(xv.w * g, 0.f);
    reinterpret_cast<float4*>(out)[i] = o;
}

// ---------------- launch ----------------
extern "C" void kernel_launch(void* const* d_in, const int* in_sizes, int n_in,
                              void* d_out, int out_size) {
    const float* x      = (const float*)d_in[0];
    const float* conv_w = (const float*)d_in[1];
    const float* bn2_g  = (const float*)d_in[2];
    const float* bn2_b  = (const float*)d_in[3];
    const float* bn2_m  = (const float*)d_in[4];
    const float* bn2_v  = (const float*)d_in[5];
    const float* cw     = (const float*)d_in[6];
    const float* scale  = (const float*)d_in[7];
    const float* bn1_g  = (const float*)d_in[8];
    const float* bn1_b  = (const float*)d_in[9];
    const float* bn1_m  = (const float*)d_in[10];
    const float* bn1_v  = (const float*)d_in[11];
    const float* fc_w   = (const float*)d_in[12];
    const float* fc_b   = (const float*)d_in[13];
    float* out = (float*)d_out;

    cudaFuncSetAttribute(k1_mma, cudaFuncAttributeMaxDynamicSharedMemorySize, SM_K1);
    cudaFuncSetAttribute(k23_mma, cudaFuncAttributeMaxDynamicSharedMemorySize, SM_K23);

    k0_zero<<<128, 256>>>();
    kc_w<<<(CC*CC + 255) / 256, 256>>>(conv_w);
    kc_cw<<<KCODE, 128>>>(cw);
    kc_x<<<dim3(NN / 32, CC / 64, BB), 256>>>(x);
    k1_mma<<<dim3(CC / 128, NN / 256, BB), 256, SM_K1>>>(bn2_g, bn2_b, bn2_m, bn2_v);
    k23_mma<<<dim3(NN / 256, BB), 256, SM_K23>>>(scale);
    k4a_feat<<<BB, CC>>>(cw, bn1_g, bn1_b, bn1_m, bn1_v, out);
    k4b_gamma<<<BB, CC>>>(fc_w, fc_b);
    k5_gate<<<(BB * CC * NN / 4 + 255) / 256, 256>>>(x, out + BB * CC);
}

// round 9
// speedup vs baseline: 2.0620x; 1.0061x over previous
#include <cuda_runtime.h>
#include <cuda_bf16.h>
#include <cstdint>

#define BB 4
#define CC 512
#define HH 128
#define WW 128
#define NN (HH*WW)      // 16384
#define KCODE 32
#define EPSF 1e-5f

// ---------------- device scratch ----------------
__device__ float g_x2[BB*NN];                               // sum_c z^2 per pixel
__device__ float g_asum[BB*KCODE];
__device__ float g_aggT[BB*CC*KCODE];                       // agg transposed [b][c][k]
__device__ float g_feat[BB*CC];
__device__ float g_gamma[BB*CC];
__device__ float g_c2[KCODE];
__device__ __align__(256) __nv_bfloat16 g_whi[CC*CC];       // conv_w split [o][c]
__device__ __align__(256) __nv_bfloat16 g_wlo[CC*CC];
__device__ __align__(256) __nv_bfloat16 g_cwhi[KCODE*CC];   // codewords split [k][c]
__device__ __align__(256) __nv_bfloat16 g_cwlo[KCODE*CC];
__device__ __align__(256) __nv_bfloat16 g_xthi[(size_t)BB*NN*CC]; // x transposed+split [b][n][c]
__device__ __align__(256) __nv_bfloat16 g_xtlo[(size_t)BB*NN*CC];
__device__ __align__(256) __nv_bfloat16 g_znhi[(size_t)BB*NN*CC]; // z split [b][n][c]
__device__ __align__(256) __nv_bfloat16 g_znlo[(size_t)BB*NN*CC];

// ---------------- helpers ----------------
__device__ __forceinline__ uint32_t smem_u32(const void* p) {
    uint32_t a;
    asm("{ .reg .u64 t; cvta.to.shared.u64 t, %1; cvt.u32.u64 %0, t; }" : "=r"(a) : "l"(p));
    return a;
}
#define SW128(off) ((off) ^ (((off) >> 3) & 0x70))
#define CP16(dst, src) asm volatile("cp.async.cg.shared.global [%0], [%1], 16;" \
    :: "r"(dst), "l"(__cvta_generic_to_global(src)) : "memory")
#define CP_COMMIT() asm volatile("cp.async.commit_group;" ::: "memory")
#define CP_WAIT0()  asm volatile("cp.async.wait_group 0;" ::: "memory")
#define CP_WAIT1()  asm volatile("cp.async.wait_group 1;" ::: "memory")

__device__ __forceinline__ void ldsm4(uint32_t addr, uint32_t* r) {
    asm volatile("ldmatrix.sync.aligned.m8n8.x4.shared.b16 {%0,%1,%2,%3}, [%4];"
        : "=r"(r[0]), "=r"(r[1]), "=r"(r[2]), "=r"(r[3]) : "r"(addr));
}
__device__ __forceinline__ void ldsm4t(uint32_t addr, uint32_t* r) {
    asm volatile("ldmatrix.sync.aligned.m8n8.x4.trans.shared.b16 {%0,%1,%2,%3}, [%4];"
        : "=r"(r[0]), "=r"(r[1]), "=r"(r[2]), "=r"(r[3]) : "r"(addr));
}
__device__ __forceinline__ void mma16816(float* c, const uint32_t* a, const uint32_t* b) {
    asm volatile("mma.sync.aligned.m16n8k16.row.col.f32.bf16.bf16.f32 "
        "{%0,%1,%2,%3}, {%4,%5,%6,%7}, {%8,%9}, {%0,%1,%2,%3};"
        : "+f"(c[0]), "+f"(c[1]), "+f"(c[2]), "+f"(c[3])
        : "r"(a[0]), "r"(a[1]), "r"(a[2]), "r"(a[3]), "r"(b[0]), "r"(b[1]));
}

// ---------------- kc_w: split conv_w + zero accumulators ----------------
__global__ void kc_w(const float* __restrict__ w) {
    int i = blockIdx.x * blockDim.x + threadIdx.x;
    int stride = gridDim.x * blockDim.x;
    if (i < CC*CC) {
        float v = w[i];
        __nv_bfloat16 hi = __float2bfloat16(v);
        __nv_bfloat16 lo = __float2bfloat16(v - __bfloat162float(hi));
        g_whi[i] = hi; g_wlo[i] = lo;
    }
    for (int j = i; j < BB*CC*KCODE; j += stride) g_aggT[j] = 0.f;
    for (int j = i; j < BB*NN; j += stride) g_x2[j] = 0.f;
    if (i < BB*KCODE) g_asum[i] = 0.f;
}

// ---------------- kc_cw: split codewords + c2 ----------------
__global__ void kc_cw(const float* __restrict__ cw) {
    __shared__ float red[128];
    int k = blockIdx.x, t = threadIdx.x;
    float s = 0.f;
    for (int i = t; i < CC; i += 128) {
        float v = cw[k*CC + i];
        __nv_bfloat16 hi = __float2bfloat16(v);
        __nv_bfloat16 lo = __float2bfloat16(v - __bfloat162float(hi));
        g_cwhi[k*CC + i] = hi; g_cwlo[k*CC + i] = lo;
        s = fmaf(v, v, s);
    }
    red[t] = s;
    __syncthreads();
    for (int st = 64; st > 0; st >>= 1) {
        if (t < st) red[t] += red[t + st];
        __syncthreads();
    }
    if (t == 0) g_c2[k] = red[0];
}

// ---------------- kc_x: transpose + split x -> [b][n][c] bf16 hi/lo ----------------
__global__ __launch_bounds__(256) void kc_x(const float* __restrict__ x) {
    __shared__ float tile[64][33];
    int b = blockIdx.z;
    int c0 = blockIdx.y * 64;
    int n0 = blockIdx.x * 32;
    int t = threadIdx.x;
    const float* xb = x + (size_t)b * CC * NN;

    int nn = t & 31, cg = t >> 5;
    #pragma unroll
    for (int i = 0; i < 8; i++) {
        int cc = cg * 8 + i;
        tile[cc][nn] = xb[(size_t)(c0 + cc) * NN + n0 + nn];
    }
    __syncthreads();
    int pc = t & 31, nr = t >> 5;
    #pragma unroll
    for (int i = 0; i < 4; i++) {
        int n = nr + 8 * i;
        float v0 = tile[pc * 2][n], v1 = tile[pc * 2 + 1][n];
        __nv_bfloat16 h0 = __float2bfloat16(v0), h1 = __float2bfloat16(v1);
        __nv_bfloat16 l0 = __float2bfloat16(v0 - __bfloat162float(h0));
        __nv_bfloat16 l1 = __float2bfloat16(v1 - __bfloat162float(h1));
        size_t idx = ((size_t)b * NN + n0 + n) * (CC/2) + (c0/2) + pc;
        reinterpret_cast<__nv_bfloat162*>(g_xthi)[idx] = __nv_bfloat162(h0, h1);
        reinterpret_cast<__nv_bfloat162*>(g_xtlo)[idx] = __nv_bfloat162(l0, l1);
    }
}

// ---------------- k1_mma: conv GEMM (split bf16) + BN2 + ReLU ----------------
// Block 128(M=o) x 256(N=n), BK=64, 8 warps in 2(m) x 4(n), warp tile 64x64.
static constexpr int K1_STAGE = 98304;
static constexpr int SM_K1 = 2 * K1_STAGE;        // 192KB

__global__ __launch_bounds__(256, 1)
void k1_mma(const float* __restrict__ bg, const float* __restrict__ bb_,
            const float* __restrict__ bm, const float* __restrict__ bv)
{
    extern __shared__ char sm[];
    uint32_t sbase = smem_u32(sm);

    int tid = threadIdx.x;
    int lane = tid & 31, wid = tid >> 5;
    int wm = wid & 1, wn = wid >> 1;
    int m0 = blockIdx.x * 128;
    int n0 = blockIdx.y * 256;
    int b  = blockIdx.z;

    auto load_stage = [&](int ch, int st) {
        uint32_t s0 = sbase + st * K1_STAGE;
        #pragma unroll
        for (int i = 0; i < 4; i++) {
            int idx = tid + 256 * i;
            int row = idx >> 3, cc8 = idx & 7;
            uint32_t dst = s0 + SW128((uint32_t)(row * 128 + cc8 * 16));
            size_t aoff = (size_t)(m0 + row) * CC + ch * 64 + cc8 * 8;
            CP16(dst,          g_whi + aoff);
            CP16(dst + 16384,  g_wlo + aoff);
        }
        #pragma unroll
        for (int i = 0; i < 8; i++) {
            int idx = tid + 256 * i;
            int row = idx >> 3, cc8 = idx & 7;
            uint32_t dst = s0 + 32768 + SW128((uint32_t)(row * 128 + cc8 * 16));
            size_t boff = ((size_t)b * NN + n0 + row) * CC + ch * 64 + cc8 * 8;
            CP16(dst,          g_xthi + boff);
            CP16(dst + 32768,  g_xtlo + boff);
        }
    };

    float acc[4][8][4];
    #pragma unroll
    for (int mi = 0; mi < 4; mi++)
        #pragma unroll
        for (int nj = 0; nj < 8; nj++)
            #pragma unroll
            for (int r = 0; r < 4; r++) acc[mi][nj][r] = 0.f;

    int rowA = lane & 15, chA = lane >> 4;
    int rowB = ((lane >> 4) << 3) + (lane & 7), chB = (lane >> 3) & 1;

    load_stage(0, 0); CP_COMMIT();

    for (int ch = 0; ch < 8; ch++) {
        CP_WAIT0();
        __syncthreads();
        if (ch < 7) { load_stage(ch + 1, (ch + 1) & 1); CP_COMMIT(); }

        uint32_t s0 = sbase + (ch & 1) * K1_STAGE;
        #pragma unroll
        for (int ks = 0; ks < 4; ks++) {
            uint32_t ahi[4][4], alo[4][4], bhi[4][4], blo[4][4];
            #pragma unroll
            for (int mi = 0; mi < 4; mi++) {
                uint32_t off = SW128((uint32_t)((wm*64 + mi*16 + rowA) * 128 + ks*32 + chA*16));
                ldsm4(s0 + off, ahi[mi]);
                ldsm4(s0 + 16384 + off, alo[mi]);
            }
            #pragma unroll
            for (int np = 0; np < 4; np++) {
                uint32_t off = 32768 + SW128((uint32_t)((wn*64 + np*16 + rowB) * 128 + ks*32 + chB*16));
                ldsm4(s0 + off, bhi[np]);
                ldsm4(s0 + 32768 + off, blo[np]);
            }
            #pragma unroll
            for (int mi = 0; mi < 4; mi++)
                #pragma unroll
                for (int nj = 0; nj < 8; nj++) {
                    const uint32_t* bh = &bhi[nj >> 1][(nj & 1) * 2];
                    const uint32_t* bl = &blo[nj >> 1][(nj & 1) * 2];
                    mma16816(acc[mi][nj], ahi[mi], bh);
                    mma16816(acc[mi][nj], ahi[mi], bl);
                    mma16816(acc[mi][nj], alo[mi], bh);
                }
        }
    }
    __syncthreads();

    // ---- Epilogue: BN2+ReLU; stage split bf16 [n 256][o 128]; x2 ----
    __nv_bfloat16* sh_hi = reinterpret_cast<__nv_bfloat16*>(sm);
    __nv_bfloat16* sh_lo = sh_hi + 256 * 136;

    float v2acc[16];
    #pragma unroll
    for (int j = 0; j < 16; j++) v2acc[j] = 0.f;

    #pragma unroll
    for (int mi = 0; mi < 4; mi++) {
        #pragma unroll
        for (int rr = 0; rr < 2; rr++) {
            int o_loc = wm*64 + mi*16 + rr*8 + (lane >> 2);
            int o = m0 + o_loc;
            float sc = bg[o] * rsqrtf(bv[o] + EPSF);
            float sh2 = bb_[o] - bm[o] * sc;
            #pragma unroll
            for (int nj = 0; nj < 8; nj++) {
                float z0 = fmaxf(fmaf(acc[mi][nj][rr*2 + 0], sc, sh2), 0.f);
                float z1 = fmaxf(fmaf(acc[mi][nj][rr*2 + 1], sc, sh2), 0.f);
                v2acc[nj*2 + 0] += z0 * z0;
                v2acc[nj*2 + 1] += z1 * z1;
                __nv_bfloat16 h0 = __float2bfloat16(z0), h1 = __float2bfloat16(z1);
                __nv_bfloat16 l0 = __float2bfloat16(z0 - __bfloat162float(h0));
                __nv_bfloat16 l1 = __float2bfloat16(z1 - __bfloat162float(h1));
                int n_loc = wn*64 + nj*8 + (lane & 3) * 2;
                sh_hi[(n_loc + 0) * 136 + o_loc] = h0;
                sh_hi[(n_loc + 1) * 136 + o_loc] = h1;
                sh_lo[(n_loc + 0) * 136 + o_loc] = l0;
                sh_lo[(n_loc + 1) * 136 + o_loc] = l1;
            }
        }
    }
    #pragma unroll
    for (int j = 0; j < 16; j++) {
        v2acc[j] += __shfl_xor_sync(0xffffffffu, v2acc[j], 4);
        v2acc[j] += __shfl_xor_sync(0xffffffffu, v2acc[j], 8);
        v2acc[j] += __shfl_xor_sync(0xffffffffu, v2acc[j], 16);
    }
    if ((lane >> 2) == 0) {
        #pragma unroll
        for (int j = 0; j < 16; j++) {
            int n_loc = wn*64 + (j >> 1) * 8 + (lane & 3) * 2 + (j & 1);
            atomicAdd(&g_x2[b*NN + n0 + n_loc], v2acc[j]);
        }
    }
    __syncthreads();
    #pragma unroll
    for (int i = 0; i < 16; i++) {
        int idx = tid + 256 * i;
        int row = idx >> 4, c16 = idx & 15;
        uint4 vh = *reinterpret_cast<const uint4*>(sh_hi + row * 136 + c16 * 8);
        uint4 vl = *reinterpret_cast<const uint4*>(sh_lo + row * 136 + c16 * 8);
        size_t di = ((size_t)b*NN + n0 + row) * CC + m0 + c16 * 8;
        *reinterpret_cast<uint4*>(&g_znhi[di]) = vh;
        *reinterpret_cast<uint4*>(&g_znlo[di]) = vl;
    }
}

// ---------------- k23_mma: fused assignment + aggregation ----------------
static constexpr int K2_CW_HI = 0;          // phase1 cw; phase2 z-stage buf 0
static constexpr int K2_CW_LO = 32768;
static constexpr int K2_ZST   = 65536;      // phase1 z double buffer (2 x 64KB)
static constexpr int K2_X2S   = 196608;     // 1KB
static constexpr int K2_ASUM  = 197632;     // 128B
static constexpr int K2_ASG   = 197760;     // assign hi 16KB | lo 16KB
static constexpr int SM_K23   = 230528;

__global__ __launch_bounds__(256, 1)
void k23_mma(const float* __restrict__ scale)
{
    extern __shared__ char sm[];
    uint32_t sbase = smem_u32(sm);
    int tid = threadIdx.x, lane = tid & 31, w = tid >> 5;
    int b = blockIdx.y;
    int n0 = blockIdx.x * 256;
    int q = lane >> 2;

    if (tid < 32) *reinterpret_cast<float*>(sm + K2_ASUM + tid*4) = 0.f;
    const uint4* cwh4 = reinterpret_cast<const uint4*>(g_cwhi);
    const uint4* cwl4 = reinterpret_cast<const uint4*>(g_cwlo);
    #pragma unroll
    for (int i = 0; i < 8; i++) {
        int idx = tid + 256 * i;
        int row = idx >> 6, cb = idx & 63;
        uint32_t off = (uint32_t)(row * 1024 + ((cb * 16) ^ ((row & 7) << 4)));
        *reinterpret_cast<uint4*>(sm + K2_CW_HI + off) = cwh4[row * 64 + cb];
        *reinterpret_cast<uint4*>(sm + K2_CW_LO + off) = cwl4[row * 64 + cb];
    }
    *reinterpret_cast<float*>(sm + K2_X2S + tid*4) = g_x2[b*NN + n0 + tid];

    // Phase-1 z loader: [256 n rows][64 c] hi/lo, 128B rows, SW128.
    auto load_z = [&](int ch, uint32_t base) {
        uint32_t s0 = sbase + base;
        #pragma unroll
        for (int i = 0; i < 8; i++) {
            int idx = tid + 256 * i;
            int row = idx >> 3, col = idx & 7;
            uint32_t dst = s0 + SW128((uint32_t)(row * 128 + col * 16));
            size_t src = ((size_t)b*NN + n0 + row) * CC + ch * 64 + col * 8;
            CP16(dst,         g_znhi + src);
            CP16(dst + 32768, g_znlo + src);
        }
    };
    // Phase-2 z loader: [32 pixel rows][512 c] hi/lo, 1KB rows, row-xor swizzle.
    auto load_z2 = [&](int ch, uint32_t base) {
        uint32_t s0 = sbase + base;
        #pragma unroll
        for (int i = 0; i < 8; i++) {
            int idx = tid + 256 * i;
            int row = idx >> 6, cb = idx & 63;
            uint32_t byte = (uint32_t)(row * 1024 + cb * 16);
            uint32_t sw = byte ^ (((uint32_t)row & 7) << 4);
            size_t src = ((size_t)b*NN + n0 + ch*32 + row) * CC + cb * 8;
            CP16(s0 + sw,         g_znhi + src);
            CP16(s0 + 32768 + sw, g_znlo + src);
        }
    };

    float acc[2][4][4];
    #pragma unroll
    for (int mf = 0; mf < 2; mf++)
        #pragma unroll
        for (int nj = 0; nj < 4; nj++)
            #pragma unroll
            for (int r = 0; r < 4; r++) acc[mf][nj][r] = 0.f;

    load_z(0, K2_ZST);
    CP_COMMIT();

    // ---- Phase 1: xc GEMM ----
    for (int ch = 0; ch < 8; ch++) {
        CP_WAIT0();
        __syncthreads();
        if (ch < 7) { load_z(ch + 1, K2_ZST + ((ch + 1) & 1) * 65536); CP_COMMIT(); }
        uint32_t zs = sbase + K2_ZST + (ch & 1) * 65536;
        #pragma unroll
        for (int ks = 0; ks < 4; ks++) {
            uint32_t ah[2][4], al[2][4], bh[2][4], bl[2][4];
            #pragma unroll
            for (int mf = 0; mf < 2; mf++) {
                int code = mf * 16 + (lane & 15);
                uint32_t off = (uint32_t)(code * 1024 +
                    ((ch*128 + ks*32 + (lane >> 4) * 16) ^ ((code & 7) << 4)));
                ldsm4(sbase + K2_CW_HI + off, ah[mf]);
                ldsm4(sbase + K2_CW_LO + off, al[mf]);
            }
            #pragma unroll
            for (int p = 0; p < 2; p++) {
                int row = w*32 + p*16 + ((lane >> 4) << 3) + (lane & 7);
                uint32_t off = SW128((uint32_t)(row * 128 + ks*32 + ((lane >> 3) & 1) * 16));
                ldsm4(zs + off, bh[p]);
                ldsm4(zs + off + 32768, bl[p]);
            }
            #pragma unroll
            for (int mf = 0; mf < 2; mf++)
                #pragma unroll
                for (int nj = 0; nj < 4; nj++) {
                    const uint32_t* Bh = &bh[nj >> 1][(nj & 1) * 2];
                    const uint32_t* Bl = &bl[nj >> 1][(nj & 1) * 2];
                    mma16816(acc[mf][nj], ah[mf], Bh);
                    mma16816(acc[mf][nj], ah[mf], Bl);
                    mma16816(acc[mf][nj], al[mf], Bh);
                }
        }
        __syncthreads();
    }

    // prefetch phase-2 pixel-chunks 0,1 (cw region + phase1 buf 0 now free)
    load_z2(0, 0);     CP_COMMIT();
    load_z2(1, 65536); CP_COMMIT();

    // ---- softmax over codes (m axis) ----
    float s4[4], c24[4];
    #pragma unroll
    for (int ci = 0; ci < 4; ci++) {
        s4[ci] = __ldg(&scale[q + 8*ci]);
        c24[ci] = g_c2[q + 8*ci];
    }
    float l[4][8];
    #pragma unroll
    for (int mf = 0; mf < 2; mf++)
        #pragma unroll
        for (int nj = 0; nj < 4; nj++)
            #pragma unroll
            for (int r = 0; r < 4; r++) {
                int ci = mf*2 + (r >> 1);
                int j  = nj*2 + (r & 1);
                int col = nj*8 + (lane & 3)*2 + (r & 1);
                float x2v = *reinterpret_cast<const float*>(sm + K2_X2S + (w*32 + col)*4);
                l[ci][j] = s4[ci] * (x2v - 2.f * acc[mf][nj][r] + c24[ci]);
            }
    float mx[8], sme[8], inv[8];
    #pragma unroll
    for (int j = 0; j < 8; j++) {
        mx[j] = fmaxf(fmaxf(l[0][j], l[1][j]), fmaxf(l[2][j], l[3][j]));
        mx[j] = fmaxf(mx[j], __shfl_xor_sync(0xffffffffu, mx[j], 4));
        mx[j] = fmaxf(mx[j], __shfl_xor_sync(0xffffffffu, mx[j], 8));
        mx[j] = fmaxf(mx[j], __shfl_xor_sync(0xffffffffu, mx[j], 16));
    }
    #pragma unroll
    for (int j = 0; j < 8; j++) {
        sme[j] = 0.f;
        #pragma unroll
        for (int ci = 0; ci < 4; ci++) {
            float e = __expf(l[ci][j] - mx[j]);
            l[ci][j] = e; sme[j] += e;
        }
        sme[j] += __shfl_xor_sync(0xffffffffu, sme[j], 4);
        sme[j] += __shfl_xor_sync(0xffffffffu, sme[j], 8);
        sme[j] += __shfl_xor_sync(0xffffffffu, sme[j], 16);
        inv[j] = 1.f / sme[j];
    }
    float apart[4];
    #pragma unroll
    for (int ci = 0; ci < 4; ci++) apart[ci] = 0.f;
    #pragma unroll
    for (int ci = 0; ci < 4; ci++)
        #pragma unroll
        for (int j = 0; j < 8; j++) {
            float av = l[ci][j] * inv[j];
            apart[ci] += av;
            int code = q + 8*ci;
            int pix = w*32 + (j >> 1)*8 + (lane & 3)*2 + (j & 1);
            __nv_bfloat16 hv = __float2bfloat16(av);
            __nv_bfloat16 lv = __float2bfloat16(av - __bfloat162float(hv));
            uint32_t aoff = (uint32_t)(code*512) +
                ((((uint32_t)pix >> 3) ^ (uint32_t)(code & 7)) << 4) + ((uint32_t)pix & 7) * 2;
            *reinterpret_cast<__nv_bfloat16*>(sm + K2_ASG + aoff) = hv;
            *reinterpret_cast<__nv_bfloat16*>(sm + K2_ASG + 16384 + aoff) = lv;
        }
    #pragma unroll
    for (int ci = 0; ci < 4; ci++) {
        apart[ci] += __shfl_xor_sync(0xffffffffu, apart[ci], 1);
        apart[ci] += __shfl_xor_sync(0xffffffffu, apart[ci], 2);
    }
    if ((lane & 3) == 0) {
        #pragma unroll
        for (int ci = 0; ci < 4; ci++)
            atomicAdd(reinterpret_cast<float*>(sm + K2_ASUM + (q + 8*ci)*4), apart[ci]);
    }
    __syncthreads();
    if (tid < 32)
        atomicAdd(&g_asum[b*KCODE + tid], *reinterpret_cast<float*>(sm + K2_ASUM + tid*4));

    // ---- Phase 2: C[m=codes 32][n=c 64/warp], contraction over 256 pixels ----
    float acc2[2][8][4];
    #pragma unroll
    for (int mf = 0; mf < 2; mf++)
        #pragma unroll
        for (int nj = 0; nj < 8; nj++)
            #pragma unroll
            for (int r = 0; r < 4; r++) acc2[mf][nj][r] = 0.f;

    for (int ch2 = 0; ch2 < 8; ch2++) {
        if (ch2 == 7) { CP_WAIT0(); } else { CP_WAIT1(); }
        __syncthreads();
        if (ch2 < 6) { load_z2(ch2 + 2, ((ch2 + 2) % 3) * 65536); CP_COMMIT(); }
        uint32_t s0 = sbase + (ch2 % 3) * 65536;

        #pragma unroll
        for (int ks = 0; ks < 2; ks++) {
            uint32_t Ah[2][4], Al[2][4], Bh[4][4], Bl[4][4];
            // A = assign frags: m=code16, k=pixel16 (plain ldsm, [code][pixel] storage)
            #pragma unroll
            for (int mf = 0; mf < 2; mf++) {
                int code = mf*16 + (lane & 15);
                uint32_t pc = (uint32_t)(ch2*4 + ks*2 + (lane >> 4));
                uint32_t ab = (uint32_t)(code*512) + ((pc ^ (uint32_t)(code & 7)) << 4);
                ldsm4(sbase + K2_ASG + ab, Ah[mf]);
                ldsm4(sbase + K2_ASG + 16384 + ab, Al[mf]);
            }
            // B = z frags via TRANS ldsm from [pixel=k][c=n] storage.
            // B matrix order: mat0=[n0-7][k0-7], mat1=[n0-7][k8-15],
            //                 mat2=[n8-15][k0-7], mat3=[n8-15][k8-15]
            // => lanes 0-7: k rows 0-7, n col 0; 8-15: k rows 8-15, n col 0;
            //    16-23: k rows 0-7, n col +8; 24-31: k rows 8-15, n col +8.
            int prow = ks*16 + ((lane >> 3) & 1)*8 + (lane & 7);
            #pragma unroll
            for (int np = 0; np < 4; np++) {
                int ccol = w*64 + np*16 + (lane >> 4)*8;
                uint32_t byte = (uint32_t)(prow * 1024 + ccol * 2);
                uint32_t sw = byte ^ (((uint32_t)prow & 7) << 4);
                ldsm4t(s0 + sw, Bh[np]);
                ldsm4t(s0 + 32768 + sw, Bl[np]);
            }
            #pragma unroll
            for (int mf = 0; mf < 2; mf++)
                #pragma unroll
                for (int nj = 0; nj < 8; nj++) {
                    const uint32_t* BH = &Bh[nj >> 1][(nj & 1) * 2];
                    const uint32_t* BL = &Bl[nj >> 1][(nj & 1) * 2];
                    mma16816(acc2[mf][nj], Ah[mf], BH);
                    mma16816(acc2[mf][nj], Ah[mf], BL);
                    mma16816(acc2[mf][nj], Al[mf], BH);
                }
        }
    }

    #pragma unroll
    for (int mf = 0; mf < 2; mf++)
        #pragma unroll
        for (int nj = 0; nj < 8; nj++)
            #pragma unroll
            for (int r = 0; r < 4; r++) {
                int code = mf*16 + (lane >> 2) + (r >> 1) * 8;
                int c = w*64 + nj*8 + (lane & 3)*2 + (r & 1);
                atomicAdd(&g_aggT[((size_t)b*CC + c)*KCODE + code], acc2[mf][nj][r]);
            }
}

// ---------------- k4a / k4b / k5 ----------------
__global__ void k4a_feat(
    const float* __restrict__ cw,
    const float* __restrict__ g1, const float* __restrict__ b1,
    const float* __restrict__ m1, const float* __restrict__ v1,
    float* __restrict__ out_feat)
{
    int b = blockIdx.x;
    int c = threadIdx.x;
    float f = 0.f;
    #pragma unroll
    for (int k = 0; k < KCODE; k++) {
        float a = g_aggT[((size_t)b*CC + c)*KCODE + k] - g_asum[b*KCODE + k] * cw[k*CC + c];
        float s = g1[k] * rsqrtf(v1[k] + EPSF);
        float e = fmaxf(fmaf(a - m1[k], s, b1[k]), 0.f);
        f += e;
    }
    f *= (1.f / KCODE);
    g_feat[b*CC + c] = f;
    out_feat[b*CC + c] = f;
}

__global__ void k4b_gamma(const float* __restrict__ fw, const float* __restrict__ fb) {
    __shared__ float fs[CC];
    int b = blockIdx.x;
    int o = threadIdx.x;
    fs[o] = g_feat[b*CC + o];
    __syncthreads();
    float acc = fb[o];
    const float* row = fw + (size_t)o * CC;
    #pragma unroll 8
    for (int c = 0; c < CC; c++) acc = fmaf(fs[c], row[c], acc);
    g_gamma[b*CC + o] = 1.f / (1.f + __expf(-acc));
}

__global__ void k5_gate(const float* __restrict__ x, float* __restrict__ out) {
    int i = blockIdx.x * blockDim.x + threadIdx.x;
    const int total4 = BB * CC * NN / 4;
    if (i >= total4) return;
    int bc = (i * 4) / NN;
    float g = 1.f + g_gamma[bc];
    float4 xv = reinterpret_cast<const float4*>(x)[i];
    float4 o;
    o.x = fmaxf(xv.x * g, 0.f);
    o.y = fmaxf(xv.y * g, 0.f);
    o.z = fmaxf(xv.z * g, 0.f);
    o.w = fmaxf(xv.w * g, 0.f);
    reinterpret_cast<float4*>(out)[i] = o;
}

// ---------------- launch ----------------
extern "C" void kernel_launch(void* const* d_in, const int* in_sizes, int n_in,
                              void* d_out, int out_size) {
    const float* x      = (const float*)d_in[0];
    const float* conv_w = (const float*)d_in[1];
    const float* bn2_g  = (const float*)d_in[2];
    const float* bn2_b  = (const float*)d_in[3];
    const float* bn2_m  = (const float*)d_in[4];
    const float* bn2_v  = (const float*)d_in[5];
    const float* cw     = (const float*)d_in[6];
    const float* scale  = (const float*)d_in[7];
    const float* bn1_g  = (const float*)d_in[8];
    const float* bn1_b  = (const float*)d_in[9];
    const float* bn1_m  = (const float*)d_in[10];
    const float* bn1_v  = (const float*)d_in[11];
    const float* fc_w   = (const float*)d_in[12];
    const float* fc_b   = (const float*)d_in[13];
    float* out = (float*)d_out;

    cudaFuncSetAttribute(k1_mma, cudaFuncAttributeMaxDynamicSharedMemorySize, SM_K1);
    cudaFuncSetAttribute(k23_mma, cudaFuncAttributeMaxDynamicSharedMemorySize, SM_K23);

    // Order chosen so k1_mma is the 4th launch (ncu profiles launch #4).
    kc_w<<<(CC*CC + 255) / 256, 256>>>(conv_w);
    kc_cw<<<KCODE, 128>>>(cw);
    kc_x<<<dim3(NN / 32, CC / 64, BB), 256>>>(x);
    k1_mma<<<dim3(CC / 128, NN / 256, BB), 256, SM_K1>>>(bn2_g, bn2_b, bn2_m, bn2_v);
    k23_mma<<<dim3(NN / 256, BB), 256, SM_K23>>>(scale);
    k4a_feat<<<BB, CC>>>(cw, bn1_g, bn1_b, bn1_m, bn1_v, out);
    k4b_gamma<<<BB, CC>>>(fc_w, fc_b);
    k5_gate<<<(BB * CC * NN / 4 + 255) / 256, 256>>>(x, out + BB * CC);
}